// round 1
// baseline (speedup 1.0000x reference)
#include <cuda_runtime.h>
#include <math.h>
#include <stdint.h>

// Problem dims
#define VOCAB 32000
#define HDIM  1024
#define EDIM  512
#define BATCH 32
#define TSEQ  64
#define IMGF  2048
#define G4    (4*HDIM)          // 4096
#define MROWS (BATCH*TSEQ)      // 2048

// ---------------- device scratch (no allocation allowed) ----------------
__device__ float g_xs  [MROWS * EDIM];    // xs[b][t][e]   4 MB
__device__ float g_pre [MROWS * G4];      // pre[b][t][g] 32 MB (reused layer0/layer1)
__device__ float g_hs0 [MROWS * HDIM];    // 8 MB
__device__ float g_hs1 [MROWS * HDIM];    // 8 MB
__device__ float g_h   [BATCH * HDIM];
__device__ float g_c   [BATCH * HDIM];
__device__ float g_gbuf[BATCH * G4];

// ---------------- kernel 1: linear(2048->512) + batchnorm over batch ----
__global__ void linbn_kernel(const float* __restrict__ img,
                             const float* __restrict__ W,
                             const float* __restrict__ bias,
                             const float* __restrict__ gamma,
                             const float* __restrict__ beta,
                             float* __restrict__ xs)
{
    const int e   = blockIdx.x;       // 512 blocks, one per feature
    const int tid = threadIdx.x;      // 256 threads
    __shared__ float wrow[IMGF];
    __shared__ float red[8];
    __shared__ float xv[BATCH];

    for (int k = tid; k < IMGF; k += 256) wrow[k] = W[(size_t)e * IMGF + k];
    __syncthreads();

    const int lane = tid & 31, warp = tid >> 5;
    for (int b = 0; b < BATCH; b++) {
        const float* row = img + (size_t)b * IMGF;
        float p = 0.f;
        for (int k = tid; k < IMGF; k += 256) p += row[k] * wrow[k];
        #pragma unroll
        for (int o = 16; o > 0; o >>= 1) p += __shfl_xor_sync(0xffffffffu, p, o);
        if (lane == 0) red[warp] = p;
        __syncthreads();
        if (tid == 0) {
            float s = 0.f;
            #pragma unroll
            for (int w = 0; w < 8; w++) s += red[w];
            xv[b] = s + bias[e];
        }
        __syncthreads();
    }

    if (tid < 32) {
        float x = xv[tid];
        float s = x, q = x * x;
        #pragma unroll
        for (int o = 16; o > 0; o >>= 1) {
            s += __shfl_xor_sync(0xffffffffu, s, o);
            q += __shfl_xor_sync(0xffffffffu, q, o);
        }
        float mu  = s * (1.f / 32.f);
        float var = q * (1.f / 32.f) - mu * mu;
        float inv = rsqrtf(var + 1e-5f);
        float y = gamma[e] * (x - mu) * inv + beta[e];
        xs[((size_t)tid * TSEQ + 0) * EDIM + e] = y;   // t = 0 slot
    }
}

// ---------------- kernel 2: embedding gather into xs[:,1:,:] ------------
__global__ void gather_kernel(const int* __restrict__ cap,
                              const float* __restrict__ emb,
                              float* __restrict__ xs)
{
    const int t = blockIdx.x + 1;   // 1..63
    const int b = blockIdx.y;
    const int tok = cap[b * TSEQ + (t - 1)];
    const float* src = emb + (size_t)tok * EDIM;
    float* dst = xs + ((size_t)b * TSEQ + t) * EDIM;
    for (int k = threadIdx.x; k < EDIM; k += 128) dst[k] = src[k];
}

// ---------------- kernel 3: generic NT GEMM: C = A * B^T + bias ---------
// A: [M,K] row-major, B: [N,K] row-major, C: [M,N]. M%128==0, N%128==0, K%16==0.
__global__ void __launch_bounds__(256, 1)
gemm_nt(const float* __restrict__ A, const float* __restrict__ B,
        float* __restrict__ C, int M, int N, int K,
        const float* __restrict__ bias1, const float* __restrict__ bias2)
{
    __shared__ float As[16][128];
    __shared__ float Bs[16][128];
    const int bn = blockIdx.x * 128;
    const int bm = blockIdx.y * 128;
    const int tid = threadIdx.x;
    const int tx = tid & 15;     // col group
    const int ty = tid >> 4;     // row group

    float acc[8][8];
    #pragma unroll
    for (int i = 0; i < 8; i++)
        #pragma unroll
        for (int j = 0; j < 8; j++) acc[i][j] = 0.f;

    for (int k0 = 0; k0 < K; k0 += 16) {
        #pragma unroll
        for (int i = 0; i < 2; i++) {
            int idx = tid + i * 256;      // 0..511 float4 slots
            int r  = idx >> 2;
            int c4 = (idx & 3) << 2;
            float4 va = *(const float4*)(A + (size_t)(bm + r) * K + k0 + c4);
            As[c4 + 0][r] = va.x; As[c4 + 1][r] = va.y;
            As[c4 + 2][r] = va.z; As[c4 + 3][r] = va.w;
            float4 vb = *(const float4*)(B + (size_t)(bn + r) * K + k0 + c4);
            Bs[c4 + 0][r] = vb.x; Bs[c4 + 1][r] = vb.y;
            Bs[c4 + 2][r] = vb.z; Bs[c4 + 3][r] = vb.w;
        }
        __syncthreads();
        #pragma unroll
        for (int kk = 0; kk < 16; kk++) {
            float a[8], b[8];
            #pragma unroll
            for (int i = 0; i < 8; i++) a[i] = As[kk][ty * 8 + i];
            #pragma unroll
            for (int j = 0; j < 8; j++) b[j] = Bs[kk][tx * 8 + j];
            #pragma unroll
            for (int i = 0; i < 8; i++)
                #pragma unroll
                for (int j = 0; j < 8; j++) acc[i][j] += a[i] * b[j];
        }
        __syncthreads();
    }

    float bv[8];
    #pragma unroll
    for (int j = 0; j < 8; j++) {
        int n = bn + tx * 8 + j;
        float v = bias1 ? bias1[n] : 0.f;
        if (bias2) v += bias2[n];
        bv[j] = v;
    }
    #pragma unroll
    for (int i = 0; i < 8; i++) {
        size_t row = (size_t)(bm + ty * 8 + i) * N + bn + tx * 8;
        #pragma unroll
        for (int j4 = 0; j4 < 2; j4++) {
            float4 o;
            o.x = acc[i][j4 * 4 + 0] + bv[j4 * 4 + 0];
            o.y = acc[i][j4 * 4 + 1] + bv[j4 * 4 + 1];
            o.z = acc[i][j4 * 4 + 2] + bv[j4 * 4 + 2];
            o.w = acc[i][j4 * 4 + 3] + bv[j4 * 4 + 3];
            *(float4*)(C + row + j4 * 4) = o;
        }
    }
}

// ---------------- kernel 4: zero h/c state ------------------------------
__global__ void zero_hc(float* __restrict__ h, float* __restrict__ c)
{
    int i = blockIdx.x * 256 + threadIdx.x;
    if (i < BATCH * HDIM) { h[i] = 0.f; c[i] = 0.f; }
}

// ---------------- kernel 5: recurrent gate GEMM -------------------------
// g[b][j] = pre_t[b][j] + sum_k h[b][k] * Whh[j][k]
// grid (G4/64, BATCH/16), 256 threads. Whh read once per 16-batch group.
__global__ void __launch_bounds__(256, 1)
lstm_gate(const float* __restrict__ pre_t,   // pre + t*G4; batch stride TSEQ*G4
          const float* __restrict__ h,
          const float* __restrict__ Whh,     // [G4][HDIM]
          float* __restrict__ g)
{
    __shared__ float hs_s[16][32];
    __shared__ float ws_s[64][33];
    const int j0  = blockIdx.x * 64;
    const int bg  = blockIdx.y * 16;
    const int tid = threadIdx.x;
    const int tx  = tid & 63;   // j within tile
    const int ty  = tid >> 6;   // 0..3 -> 4 batches each

    float acc0 = 0.f, acc1 = 0.f, acc2 = 0.f, acc3 = 0.f;

    for (int k0 = 0; k0 < HDIM; k0 += 32) {
        #pragma unroll
        for (int idx = tid; idx < 512; idx += 256) {
            int bb = idx >> 5, kk = idx & 31;
            hs_s[bb][kk] = h[(size_t)(bg + bb) * HDIM + k0 + kk];
        }
        #pragma unroll
        for (int idx = tid; idx < 2048; idx += 256) {
            int jj = idx >> 5, kk = idx & 31;
            ws_s[jj][kk] = Whh[(size_t)(j0 + jj) * HDIM + k0 + kk];
        }
        __syncthreads();
        #pragma unroll
        for (int kk = 0; kk < 32; kk++) {
            float w = ws_s[tx][kk];
            acc0 += hs_s[ty * 4 + 0][kk] * w;
            acc1 += hs_s[ty * 4 + 1][kk] * w;
            acc2 += hs_s[ty * 4 + 2][kk] * w;
            acc3 += hs_s[ty * 4 + 3][kk] * w;
        }
        __syncthreads();
    }

    float r[4] = {acc0, acc1, acc2, acc3};
    #pragma unroll
    for (int u = 0; u < 4; u++) {
        int b = bg + ty * 4 + u;
        g[(size_t)b * G4 + j0 + tx] =
            r[u] + pre_t[(size_t)b * (TSEQ * G4) + j0 + tx];
    }
}

// ---------------- kernel 6: LSTM pointwise update -----------------------
__global__ void lstm_pointwise(const float* __restrict__ g,
                               float* __restrict__ h,
                               float* __restrict__ c,
                               float* __restrict__ hs_out, int t)
{
    int idx = blockIdx.x * 256 + threadIdx.x;   // 32768 total
    if (idx >= BATCH * HDIM) return;
    int b = idx >> 10, u = idx & (HDIM - 1);
    const float* gb = g + (size_t)b * G4;
    float gi = gb[u];
    float gf = gb[HDIM + u];
    float gg = gb[2 * HDIM + u];
    float go = gb[3 * HDIM + u];
    float si = 1.f / (1.f + expf(-gi));
    float sf = 1.f / (1.f + expf(-gf));
    float so = 1.f / (1.f + expf(-go));
    float cn = sf * c[idx] + si * tanhf(gg);
    float hn = so * tanhf(cn);
    c[idx] = cn;
    h[idx] = hn;
    hs_out[((size_t)b * TSEQ + t) * HDIM + u] = hn;
}

// ---------------- host launch --------------------------------------------
extern "C" void kernel_launch(void* const* d_in, const int* in_sizes, int n_in,
                              void* d_out, int out_size)
{
    const float* image   = (const float*)d_in[0];
    const int*   caps    = (const int*)  d_in[1];
    const float* lin_W   = (const float*)d_in[2];
    const float* lin_b   = (const float*)d_in[3];
    const float* bn_g    = (const float*)d_in[4];
    const float* bn_b    = (const float*)d_in[5];
    const float* emb     = (const float*)d_in[6];
    const float* Wih0    = (const float*)d_in[7];
    const float* Whh0    = (const float*)d_in[8];
    const float* bih0    = (const float*)d_in[9];
    const float* bhh0    = (const float*)d_in[10];
    const float* Wih1    = (const float*)d_in[11];
    const float* Whh1    = (const float*)d_in[12];
    const float* bih1    = (const float*)d_in[13];
    const float* bhh1    = (const float*)d_in[14];
    const float* fc_W    = (const float*)d_in[15];
    const float* fc_b    = (const float*)d_in[16];
    float* out = (float*)d_out;

    float *xs, *pre, *hs0, *hs1, *h, *c, *gbuf;
    cudaGetSymbolAddress((void**)&xs,  g_xs);
    cudaGetSymbolAddress((void**)&pre, g_pre);
    cudaGetSymbolAddress((void**)&hs0, g_hs0);
    cudaGetSymbolAddress((void**)&hs1, g_hs1);
    cudaGetSymbolAddress((void**)&h,   g_h);
    cudaGetSymbolAddress((void**)&c,   g_c);
    cudaGetSymbolAddress((void**)&gbuf,g_gbuf);

    // 1) linear + batchnorm -> xs[:,0,:]
    linbn_kernel<<<EDIM, 256>>>(image, lin_W, lin_b, bn_g, bn_b, xs);
    // 2) embedding gather -> xs[:,1:,:]
    gather_kernel<<<dim3(TSEQ - 1, BATCH), 128>>>(caps, emb, xs);

    // 3) pre0 = xs @ Wih0^T + bih0 + bhh0
    gemm_nt<<<dim3(G4 / 128, MROWS / 128), 256>>>(xs, Wih0, pre,
                                                  MROWS, G4, EDIM, bih0, bhh0);

    // 4) layer-0 recurrence
    zero_hc<<<(BATCH * HDIM + 255) / 256, 256>>>(h, c);
    for (int t = 0; t < TSEQ; t++) {
        lstm_gate<<<dim3(G4 / 64, BATCH / 16), 256>>>(pre + (size_t)t * G4, h, Whh0, gbuf);
        lstm_pointwise<<<(BATCH * HDIM + 255) / 256, 256>>>(gbuf, h, c, hs0, t);
    }

    // 5) pre1 = hs0 @ Wih1^T + bih1 + bhh1
    gemm_nt<<<dim3(G4 / 128, MROWS / 128), 256>>>(hs0, Wih1, pre,
                                                  MROWS, G4, HDIM, bih1, bhh1);

    // 6) layer-1 recurrence
    zero_hc<<<(BATCH * HDIM + 255) / 256, 256>>>(h, c);
    for (int t = 0; t < TSEQ; t++) {
        lstm_gate<<<dim3(G4 / 64, BATCH / 16), 256>>>(pre + (size_t)t * G4, h, Whh1, gbuf);
        lstm_pointwise<<<(BATCH * HDIM + 255) / 256, 256>>>(gbuf, h, c, hs1, t);
    }

    // 7) logits = hs1 @ fc_W^T + fc_b
    gemm_nt<<<dim3(VOCAB / 128, MROWS / 128), 256>>>(hs1, fc_W, out,
                                                     MROWS, VOCAB, HDIM, fc_b, nullptr);
}

// round 3
// speedup vs baseline: 1.5251x; 1.5251x over previous
#include <cuda_runtime.h>
#include <cuda_bf16.h>
#include <math.h>
#include <stdint.h>

// Problem dims
#define VOCAB 32000
#define HDIM  1024
#define EDIM  512
#define BATCH 32
#define TSEQ  64
#define IMGF  2048
#define G4    (4*HDIM)          // 4096
#define MROWS (BATCH*TSEQ)      // 2048

// ---------------- device scratch (no allocation allowed) ----------------
__device__ float g_xs  [MROWS * EDIM];
__device__ float g_pre [MROWS * G4];
__device__ float g_hs0 [MROWS * HDIM];
__device__ float g_hs1 [MROWS * HDIM];
__device__ float g_h   [BATCH * HDIM];
__device__ float g_c   [BATCH * HDIM];

// bf16 hi/lo decompositions
__device__ __nv_bfloat16 g_ah [MROWS * HDIM];
__device__ __nv_bfloat16 g_al [MROWS * HDIM];
__device__ __nv_bfloat16 g_w0h[G4 * EDIM];
__device__ __nv_bfloat16 g_w0l[G4 * EDIM];
__device__ __nv_bfloat16 g_w1h[G4 * HDIM];
__device__ __nv_bfloat16 g_w1l[G4 * HDIM];
__device__ __nv_bfloat16 g_fh [VOCAB * HDIM];
__device__ __nv_bfloat16 g_fl [VOCAB * HDIM];

// ======================= helpers =========================================
__device__ __forceinline__ uint32_t smem_u32(const void* p) {
    uint32_t a;
    asm("{ .reg .u64 t; cvta.to.shared.u64 t, %1; cvt.u32.u64 %0, t; }"
        : "=r"(a) : "l"(p));
    return a;
}
#define SWZ(x) ((x) ^ (((x) >> 3) & 0x70))

__device__ __forceinline__ void cpa16(uint32_t dst, const void* src) {
    asm volatile("cp.async.cg.shared.global [%0], [%1], 16;"
                 :: "r"(dst), "l"(src) : "memory");
}
#define CP_COMMIT() asm volatile("cp.async.commit_group;" ::: "memory")
#define CP_WAIT0()  asm volatile("cp.async.wait_group 0;" ::: "memory")
#define CP_WAIT1()  asm volatile("cp.async.wait_group 1;" ::: "memory")

__device__ __forceinline__ void ldsm_x4(uint32_t* r, uint32_t addr) {
    asm volatile("ldmatrix.sync.aligned.m8n8.x4.shared.b16 {%0,%1,%2,%3}, [%4];"
                 : "=r"(r[0]), "=r"(r[1]), "=r"(r[2]), "=r"(r[3]) : "r"(addr));
}
__device__ __forceinline__ void mma_bf16(float* c, const uint32_t* a, const uint32_t* b) {
    asm volatile(
        "mma.sync.aligned.m16n8k16.row.col.f32.bf16.bf16.f32 "
        "{%0,%1,%2,%3}, {%4,%5,%6,%7}, {%8,%9}, {%0,%1,%2,%3};"
        : "+f"(c[0]), "+f"(c[1]), "+f"(c[2]), "+f"(c[3])
        : "r"(a[0]), "r"(a[1]), "r"(a[2]), "r"(a[3]), "r"(b[0]), "r"(b[1]));
}

// ============== fp32 -> bf16 hi/lo split conversion ======================
__global__ void cvt_hilo(const float* __restrict__ x,
                         __nv_bfloat16* __restrict__ hi,
                         __nv_bfloat16* __restrict__ lo, int n)
{
    int i = (blockIdx.x * 256 + threadIdx.x) * 4;
    if (i >= n) return;
    float4 v = *(const float4*)(x + i);
    __nv_bfloat16 h0 = __float2bfloat16(v.x);
    __nv_bfloat16 h1 = __float2bfloat16(v.y);
    __nv_bfloat16 h2 = __float2bfloat16(v.z);
    __nv_bfloat16 h3 = __float2bfloat16(v.w);
    __nv_bfloat16 l0 = __float2bfloat16(v.x - __bfloat162float(h0));
    __nv_bfloat16 l1 = __float2bfloat16(v.y - __bfloat162float(h1));
    __nv_bfloat16 l2 = __float2bfloat16(v.z - __bfloat162float(h2));
    __nv_bfloat16 l3 = __float2bfloat16(v.w - __bfloat162float(h3));
    __nv_bfloat162 ph0; ph0.x = h0; ph0.y = h1;
    __nv_bfloat162 ph1; ph1.x = h2; ph1.y = h3;
    __nv_bfloat162 pl0; pl0.x = l0; pl0.y = l1;
    __nv_bfloat162 pl1; pl1.x = l2; pl1.y = l3;
    *(__nv_bfloat162*)(hi + i)     = ph0;
    *(__nv_bfloat162*)(hi + i + 2) = ph1;
    *(__nv_bfloat162*)(lo + i)     = pl0;
    *(__nv_bfloat162*)(lo + i + 2) = pl1;
}

// ============== HMMA bf16x3 GEMM: C = A*B^T + bias =======================
// A[M,K], B[N,K] as bf16 hi/lo. C fp32 [M,N]. grid(M/128, N/128), 256 thr.
// K-chunk 64; smem: 2 stages x 4 tensors x 16KB = 128KB dyn.
#define TILE 16384
__global__ void __launch_bounds__(256, 1)
gemm_bf16x3(const __nv_bfloat16* __restrict__ Ah, const __nv_bfloat16* __restrict__ Al,
            const __nv_bfloat16* __restrict__ Bh, const __nv_bfloat16* __restrict__ Bl,
            float* __restrict__ C, int M, int N, int K,
            const float* __restrict__ bias1, const float* __restrict__ bias2)
{
    extern __shared__ char dsm[];
    const int tid  = threadIdx.x;
    const int wid  = tid >> 5;
    const int lane = tid & 31;
    const int bm = blockIdx.x * 128;
    const int bn = blockIdx.y * 128;
    const int wm = (wid & 1) * 64;
    const int wn = (wid >> 1) * 32;
    const int nk = K >> 6;

    // 1024-align dyn smem
    uint32_t dyn = smem_u32(dsm);
    uint32_t sb0 = (dyn + 1023u) & ~1023u;

    float acc[4][4][4];
    #pragma unroll
    for (int i = 0; i < 4; i++)
        #pragma unroll
        for (int j = 0; j < 4; j++)
            #pragma unroll
            for (int r = 0; r < 4; r++) acc[i][j][r] = 0.f;

    // loader coords: 16 chunks/thread, chunk = tensor*1024 + r*8 + c
    // issue loads for stage s, k-chunk kt
    auto issue_load = [&](int kt) {
        const int s = kt & 1;
        const uint32_t st = sb0 + s * (4 * TILE);
        const size_t koff = (size_t)kt * 64;
        #pragma unroll
        for (int i = 0; i < 16; i++) {
            int chunk = i * 256 + tid;
            int tensor = chunk >> 10;
            int cid = chunk & 1023;
            int r = cid >> 3;
            int cc = cid & 7;
            uint32_t dst = st + tensor * TILE + SWZ((uint32_t)(r * 128 + cc * 16));
            const __nv_bfloat16* src;
            if (tensor == 0)      src = Ah + (size_t)(bm + r) * K + koff + cc * 8;
            else if (tensor == 1) src = Al + (size_t)(bm + r) * K + koff + cc * 8;
            else if (tensor == 2) src = Bh + (size_t)(bn + r) * K + koff + cc * 8;
            else                  src = Bl + (size_t)(bn + r) * K + koff + cc * 8;
            cpa16(dst, src);
        }
        CP_COMMIT();
    };

    issue_load(0);

    // lane-constant fragment address pieces
    const int a_row = wm + (lane & 15);            // + mi*16
    const int a_k8  = (lane >> 4) * 8;             // + ks*16
    const int b_row = wn + ((lane >> 4) & 1) * 8 + (lane & 7);   // + p*16
    const int b_k8  = ((lane >> 3) & 1) * 8;       // + ks*16

    for (int kt = 0; kt < nk; kt++) {
        const int s = kt & 1;
        if (kt + 1 < nk) { issue_load(kt + 1); CP_WAIT1(); }
        else             { CP_WAIT0(); }
        __syncthreads();

        const uint32_t st  = sb0 + s * (4 * TILE);
        const uint32_t sAh = st;
        const uint32_t sAl = st + TILE;
        const uint32_t sBh = st + 2 * TILE;
        const uint32_t sBl = st + 3 * TILE;

        #pragma unroll
        for (int ks = 0; ks < 4; ks++) {
            const int kb = ks * 16;
            uint32_t aH[4][4], aL[4][4];
            uint32_t bH[8], bL[8];
            #pragma unroll
            for (int mi = 0; mi < 4; mi++) {
                uint32_t off = SWZ((uint32_t)((a_row + mi * 16) * 128 + (kb + a_k8) * 2));
                ldsm_x4(aH[mi], sAh + off);
                ldsm_x4(aL[mi], sAl + off);
            }
            #pragma unroll
            for (int p = 0; p < 2; p++) {
                uint32_t off = SWZ((uint32_t)((b_row + p * 16) * 128 + (kb + b_k8) * 2));
                ldsm_x4(&bH[p * 4], sBh + off);
                ldsm_x4(&bL[p * 4], sBl + off);
            }
            #pragma unroll
            for (int mi = 0; mi < 4; mi++)
                #pragma unroll
                for (int nj = 0; nj < 4; nj++) {
                    mma_bf16(acc[mi][nj], aH[mi], &bH[nj * 2]);
                    mma_bf16(acc[mi][nj], aH[mi], &bL[nj * 2]);
                    mma_bf16(acc[mi][nj], aL[mi], &bH[nj * 2]);
                }
        }
        __syncthreads();
    }

    // epilogue: thread holds c rows (lane>>2, +8), cols (lane&3)*2, +1
    #pragma unroll
    for (int nj = 0; nj < 4; nj++) {
        const int col = bn + wn + nj * 8 + (lane & 3) * 2;
        float b0 = 0.f, b1 = 0.f;
        if (bias1) { b0 += bias1[col]; b1 += bias1[col + 1]; }
        if (bias2) { b0 += bias2[col]; b1 += bias2[col + 1]; }
        #pragma unroll
        for (int mi = 0; mi < 4; mi++) {
            const int r0 = bm + wm + mi * 16 + (lane >> 2);
            float2 v0 = make_float2(acc[mi][nj][0] + b0, acc[mi][nj][1] + b1);
            float2 v1 = make_float2(acc[mi][nj][2] + b0, acc[mi][nj][3] + b1);
            *(float2*)(C + (size_t)r0 * N + col)       = v0;
            *(float2*)(C + (size_t)(r0 + 8) * N + col) = v1;
        }
    }
}

// ---------------- kernel: linear(2048->512) + batchnorm over batch ------
__global__ void linbn_kernel(const float* __restrict__ img,
                             const float* __restrict__ W,
                             const float* __restrict__ bias,
                             const float* __restrict__ gamma,
                             const float* __restrict__ beta,
                             float* __restrict__ xs)
{
    const int e   = blockIdx.x;
    const int tid = threadIdx.x;
    __shared__ float wrow[IMGF];
    __shared__ float red[8];
    __shared__ float xv[BATCH];

    for (int k = tid; k < IMGF; k += 256) wrow[k] = W[(size_t)e * IMGF + k];
    __syncthreads();

    const int lane = tid & 31, warp = tid >> 5;
    for (int b = 0; b < BATCH; b++) {
        const float* row = img + (size_t)b * IMGF;
        float p = 0.f;
        for (int k = tid; k < IMGF; k += 256) p += row[k] * wrow[k];
        #pragma unroll
        for (int o = 16; o > 0; o >>= 1) p += __shfl_xor_sync(0xffffffffu, p, o);
        if (lane == 0) red[warp] = p;
        __syncthreads();
        if (tid == 0) {
            float s = 0.f;
            #pragma unroll
            for (int w = 0; w < 8; w++) s += red[w];
            xv[b] = s + bias[e];
        }
        __syncthreads();
    }

    if (tid < 32) {
        float x = xv[tid];
        float s = x, q = x * x;
        #pragma unroll
        for (int o = 16; o > 0; o >>= 1) {
            s += __shfl_xor_sync(0xffffffffu, s, o);
            q += __shfl_xor_sync(0xffffffffu, q, o);
        }
        float mu  = s * (1.f / 32.f);
        float var = q * (1.f / 32.f) - mu * mu;
        float inv = rsqrtf(var + 1e-5f);
        float y = gamma[e] * (x - mu) * inv + beta[e];
        xs[((size_t)tid * TSEQ + 0) * EDIM + e] = y;
    }
}

// ---------------- kernel: embedding gather into xs[:,1:,:] --------------
__global__ void gather_kernel(const int* __restrict__ cap,
                              const float* __restrict__ emb,
                              float* __restrict__ xs)
{
    const int t = blockIdx.x + 1;
    const int b = blockIdx.y;
    const int tok = cap[b * TSEQ + (t - 1)];
    const float* src = emb + (size_t)tok * EDIM;
    float* dst = xs + ((size_t)b * TSEQ + t) * EDIM;
    for (int k = threadIdx.x; k < EDIM; k += 128) dst[k] = src[k];
}

// ---------------- kernel: zero h/c state --------------------------------
__global__ void zero_hc(float* __restrict__ h, float* __restrict__ c)
{
    int i = blockIdx.x * 256 + threadIdx.x;
    if (i < BATCH * HDIM) { h[i] = 0.f; c[i] = 0.f; }
}

// ---------------- fused LSTM step: gate GEMM + pointwise ----------------
__global__ void __launch_bounds__(256, 1)
lstm_step(const float* __restrict__ pre_t,   // pre + t*G4; batch stride TSEQ*G4
          const float* __restrict__ Whh,     // [G4][HDIM]
          float* __restrict__ h,
          float* __restrict__ c,
          float* __restrict__ hs_out, int t, int skip)
{
    __shared__ float w_s[32][33];
    __shared__ __align__(16) float h_s[32][36];
    __shared__ float g_s[32][33];

    const int tid = threadIdx.x;
    const int jj  = tid & 31;
    const int bq  = tid >> 5;
    const int u0  = blockIdx.x * 8;
    const int jrow = (jj >> 3) * HDIM + u0 + (jj & 7);

    float a0 = 0.f, a1 = 0.f, a2 = 0.f, a3 = 0.f;
    if (!skip) {
        for (int k0 = 0; k0 < HDIM; k0 += 32) {
            __syncthreads();
            #pragma unroll
            for (int i = 0; i < 4; i++) {
                int idx = tid + i * 256;
                int rr = idx >> 5, kk = idx & 31;
                h_s[kk][rr] = h[rr * HDIM + k0 + kk];
                int wr = (rr >> 3) * HDIM + u0 + (rr & 7);
                w_s[rr][kk] = Whh[(size_t)wr * HDIM + k0 + kk];
            }
            __syncthreads();
            #pragma unroll
            for (int kk = 0; kk < 32; kk++) {
                float w = w_s[jj][kk];
                float4 hv = *(const float4*)&h_s[kk][bq * 4];
                a0 += w * hv.x; a1 += w * hv.y;
                a2 += w * hv.z; a3 += w * hv.w;
            }
        }
        __syncthreads();
    }

    {
        const int b0 = bq * 4;
        const size_t bs = (size_t)TSEQ * G4;
        g_s[jj][b0 + 0] = a0 + pre_t[(size_t)(b0 + 0) * bs + jrow];
        g_s[jj][b0 + 1] = a1 + pre_t[(size_t)(b0 + 1) * bs + jrow];
        g_s[jj][b0 + 2] = a2 + pre_t[(size_t)(b0 + 2) * bs + jrow];
        g_s[jj][b0 + 3] = a3 + pre_t[(size_t)(b0 + 3) * bs + jrow];
    }
    __syncthreads();

    {
        const int u = tid >> 5;
        const int b = tid & 31;
        float gi = g_s[u][b];
        float gf = g_s[8 + u][b];
        float gg = g_s[16 + u][b];
        float go = g_s[24 + u][b];
        float si = 1.f / (1.f + expf(-gi));
        float sf = 1.f / (1.f + expf(-gf));
        float so = 1.f / (1.f + expf(-go));
        const int ug = u0 + u;
        const size_t ci = (size_t)b * HDIM + ug;
        float cn = sf * c[ci] + si * tanhf(gg);
        float hn = so * tanhf(cn);
        c[ci] = cn;
        h[ci] = hn;
        hs_out[((size_t)b * TSEQ + t) * HDIM + ug] = hn;
    }
}

// ---------------- host launch --------------------------------------------
extern "C" void kernel_launch(void* const* d_in, const int* in_sizes, int n_in,
                              void* d_out, int out_size)
{
    const float* image = (const float*)d_in[0];
    const int*   caps  = (const int*)  d_in[1];
    const float* lin_W = (const float*)d_in[2];
    const float* lin_b = (const float*)d_in[3];
    const float* bn_g  = (const float*)d_in[4];
    const float* bn_b  = (const float*)d_in[5];
    const float* emb   = (const float*)d_in[6];
    const float* Wih0  = (const float*)d_in[7];
    const float* Whh0  = (const float*)d_in[8];
    const float* bih0  = (const float*)d_in[9];
    const float* bhh0  = (const float*)d_in[10];
    const float* Wih1  = (const float*)d_in[11];
    const float* Whh1  = (const float*)d_in[12];
    const float* bih1  = (const float*)d_in[13];
    const float* bhh1  = (const float*)d_in[14];
    const float* fc_W  = (const float*)d_in[15];
    const float* fc_b  = (const float*)d_in[16];
    float* out = (float*)d_out;

    float *xs, *pre, *hs0, *hs1, *h, *c;
    __nv_bfloat16 *ah, *al, *w0h, *w0l, *w1h, *w1l, *fh, *fl;
    cudaGetSymbolAddress((void**)&xs,  g_xs);
    cudaGetSymbolAddress((void**)&pre, g_pre);
    cudaGetSymbolAddress((void**)&hs0, g_hs0);
    cudaGetSymbolAddress((void**)&hs1, g_hs1);
    cudaGetSymbolAddress((void**)&h,   g_h);
    cudaGetSymbolAddress((void**)&c,   g_c);
    cudaGetSymbolAddress((void**)&ah,  g_ah);
    cudaGetSymbolAddress((void**)&al,  g_al);
    cudaGetSymbolAddress((void**)&w0h, g_w0h);
    cudaGetSymbolAddress((void**)&w0l, g_w0l);
    cudaGetSymbolAddress((void**)&w1h, g_w1h);
    cudaGetSymbolAddress((void**)&w1l, g_w1l);
    cudaGetSymbolAddress((void**)&fh,  g_fh);
    cudaGetSymbolAddress((void**)&fl,  g_fl);

    static int smem_set = 0;
    const int GEMM_SMEM = 2 * 4 * TILE + 1024;   // 132KB
    if (!smem_set) {
        cudaFuncSetAttribute(gemm_bf16x3,
                             cudaFuncAttributeMaxDynamicSharedMemorySize, GEMM_SMEM);
        smem_set = 1;
    }

    // weight conversions
    cvt_hilo<<<(G4 * EDIM / 4 + 255) / 256, 256>>>(Wih0, w0h, w0l, G4 * EDIM);
    cvt_hilo<<<(G4 * HDIM / 4 + 255) / 256, 256>>>(Wih1, w1h, w1l, G4 * HDIM);
    cvt_hilo<<<(VOCAB * HDIM / 4 + 255) / 256, 256>>>(fc_W, fh, fl, VOCAB * HDIM);

    // xs = [bn(linear(image)), emb gather]
    linbn_kernel<<<EDIM, 256>>>(image, lin_W, lin_b, bn_g, bn_b, xs);
    gather_kernel<<<dim3(TSEQ - 1, BATCH), 128>>>(caps, emb, xs);

    // pre0 = xs @ Wih0^T + bih0 + bhh0
    cvt_hilo<<<(MROWS * EDIM / 4 + 255) / 256, 256>>>(xs, ah, al, MROWS * EDIM);
    gemm_bf16x3<<<dim3(MROWS / 128, G4 / 128), 256, GEMM_SMEM>>>(
        ah, al, w0h, w0l, pre, MROWS, G4, EDIM, bih0, bhh0);

    // layer-0 recurrence
    zero_hc<<<(BATCH * HDIM + 255) / 256, 256>>>(h, c);
    for (int t = 0; t < TSEQ; t++)
        lstm_step<<<128, 256>>>(pre + (size_t)t * G4, Whh0, h, c, hs0, t, t == 0);

    // pre1 = hs0 @ Wih1^T + bih1 + bhh1
    cvt_hilo<<<(MROWS * HDIM / 4 + 255) / 256, 256>>>(hs0, ah, al, MROWS * HDIM);
    gemm_bf16x3<<<dim3(MROWS / 128, G4 / 128), 256, GEMM_SMEM>>>(
        ah, al, w1h, w1l, pre, MROWS, G4, HDIM, bih1, bhh1);

    // layer-1 recurrence
    zero_hc<<<(BATCH * HDIM + 255) / 256, 256>>>(h, c);
    for (int t = 0; t < TSEQ; t++)
        lstm_step<<<128, 256>>>(pre + (size_t)t * G4, Whh1, h, c, hs1, t, t == 0);

    // logits = hs1 @ fc_W^T + fc_b
    cvt_hilo<<<(MROWS * HDIM / 4 + 255) / 256, 256>>>(hs1, ah, al, MROWS * HDIM);
    gemm_bf16x3<<<dim3(MROWS / 128, VOCAB / 128), 256, GEMM_SMEM>>>(
        ah, al, fh, fl, out, MROWS, VOCAB, HDIM, fc_b, nullptr);
}

// round 4
// speedup vs baseline: 1.7523x; 1.1490x over previous
#include <cuda_runtime.h>
#include <cuda_bf16.h>
#include <math.h>
#include <stdint.h>

// Problem dims
#define VOCAB 32000
#define HDIM  1024
#define EDIM  512
#define BATCH 32
#define TSEQ  64
#define IMGF  2048
#define G4    (4*HDIM)          // 4096
#define MROWS (BATCH*TSEQ)      // 2048
#define NBLK  128               // persistent recurrence CTAs

// ---------------- device scratch (no allocation allowed) ----------------
__device__ float g_xs  [MROWS * EDIM];
__device__ float g_pre [MROWS * G4];     // time-major: [t][b][G4]
__device__ float g_hs0 [MROWS * HDIM];
__device__ float g_hs1 [MROWS * HDIM];
__device__ float g_h   [BATCH * HDIM];
__device__ float g_c   [BATCH * HDIM];
__device__ unsigned g_bar_ctr;

// bf16 hi/lo decompositions
__device__ __nv_bfloat16 g_ah [MROWS * HDIM];
__device__ __nv_bfloat16 g_al [MROWS * HDIM];
__device__ __nv_bfloat16 g_w0h[G4 * EDIM];
__device__ __nv_bfloat16 g_w0l[G4 * EDIM];
__device__ __nv_bfloat16 g_w1h[G4 * HDIM];
__device__ __nv_bfloat16 g_w1l[G4 * HDIM];
__device__ __nv_bfloat16 g_fh [VOCAB * HDIM];
__device__ __nv_bfloat16 g_fl [VOCAB * HDIM];

// ======================= helpers =========================================
__device__ __forceinline__ uint32_t smem_u32(const void* p) {
    uint32_t a;
    asm("{ .reg .u64 t; cvta.to.shared.u64 t, %1; cvt.u32.u64 %0, t; }"
        : "=r"(a) : "l"(p));
    return a;
}
#define SWZ(x) ((x) ^ (((x) >> 3) & 0x70))

__device__ __forceinline__ void cpa16(uint32_t dst, const void* src) {
    asm volatile("cp.async.cg.shared.global [%0], [%1], 16;"
                 :: "r"(dst), "l"(src) : "memory");
}
#define CP_COMMIT() asm volatile("cp.async.commit_group;" ::: "memory")
#define CP_WAIT0()  asm volatile("cp.async.wait_group 0;" ::: "memory")
#define CP_WAIT1()  asm volatile("cp.async.wait_group 1;" ::: "memory")

__device__ __forceinline__ void ldsm_x4(uint32_t* r, uint32_t addr) {
    asm volatile("ldmatrix.sync.aligned.m8n8.x4.shared.b16 {%0,%1,%2,%3}, [%4];"
                 : "=r"(r[0]), "=r"(r[1]), "=r"(r[2]), "=r"(r[3]) : "r"(addr));
}
__device__ __forceinline__ void mma_bf16(float* c, const uint32_t* a, const uint32_t* b) {
    asm volatile(
        "mma.sync.aligned.m16n8k16.row.col.f32.bf16.bf16.f32 "
        "{%0,%1,%2,%3}, {%4,%5,%6,%7}, {%8,%9}, {%0,%1,%2,%3};"
        : "+f"(c[0]), "+f"(c[1]), "+f"(c[2]), "+f"(c[3])
        : "r"(a[0]), "r"(a[1]), "r"(a[2]), "r"(a[3]), "r"(b[0]), "r"(b[1]));
}

// ============== fp32 -> bf16 hi/lo split conversion ======================
__global__ void cvt_hilo(const float* __restrict__ x,
                         __nv_bfloat16* __restrict__ hi,
                         __nv_bfloat16* __restrict__ lo, int n)
{
    int i = (blockIdx.x * 256 + threadIdx.x) * 4;
    if (i >= n) return;
    float4 v = *(const float4*)(x + i);
    __nv_bfloat16 h0 = __float2bfloat16(v.x);
    __nv_bfloat16 h1 = __float2bfloat16(v.y);
    __nv_bfloat16 h2 = __float2bfloat16(v.z);
    __nv_bfloat16 h3 = __float2bfloat16(v.w);
    __nv_bfloat16 l0 = __float2bfloat16(v.x - __bfloat162float(h0));
    __nv_bfloat16 l1 = __float2bfloat16(v.y - __bfloat162float(h1));
    __nv_bfloat16 l2 = __float2bfloat16(v.z - __bfloat162float(h2));
    __nv_bfloat16 l3 = __float2bfloat16(v.w - __bfloat162float(h3));
    __nv_bfloat162 ph0; ph0.x = h0; ph0.y = h1;
    __nv_bfloat162 ph1; ph1.x = h2; ph1.y = h3;
    __nv_bfloat162 pl0; pl0.x = l0; pl0.y = l1;
    __nv_bfloat162 pl1; pl1.x = l2; pl1.y = l3;
    *(__nv_bfloat162*)(hi + i)     = ph0;
    *(__nv_bfloat162*)(hi + i + 2) = ph1;
    *(__nv_bfloat162*)(lo + i)     = pl0;
    *(__nv_bfloat162*)(lo + i + 2) = pl1;
}

// ============== HMMA bf16x3 GEMM: C = A*B^T + bias =======================
// A[M,K], B[N,K] as bf16 hi/lo. C fp32 [M,N]. grid(M/128, N/128), 256 thr.
// permute: output row m -> (m%64)*32 + m/64   (b*T+t -> t*B+b time-major)
#define TILE 16384
__global__ void __launch_bounds__(256, 1)
gemm_bf16x3(const __nv_bfloat16* __restrict__ Ah, const __nv_bfloat16* __restrict__ Al,
            const __nv_bfloat16* __restrict__ Bh, const __nv_bfloat16* __restrict__ Bl,
            float* __restrict__ C, int M, int N, int K,
            const float* __restrict__ bias1, const float* __restrict__ bias2,
            int permute)
{
    extern __shared__ char dsm[];
    const int tid  = threadIdx.x;
    const int wid  = tid >> 5;
    const int lane = tid & 31;
    const int bm = blockIdx.x * 128;
    const int bn = blockIdx.y * 128;
    const int wm = (wid & 1) * 64;
    const int wn = (wid >> 1) * 32;
    const int nk = K >> 6;

    uint32_t dyn = smem_u32(dsm);
    uint32_t sb0 = (dyn + 1023u) & ~1023u;

    float acc[4][4][4];
    #pragma unroll
    for (int i = 0; i < 4; i++)
        #pragma unroll
        for (int j = 0; j < 4; j++)
            #pragma unroll
            for (int r = 0; r < 4; r++) acc[i][j][r] = 0.f;

    auto issue_load = [&](int kt) {
        const int s = kt & 1;
        const uint32_t st = sb0 + s * (4 * TILE);
        const size_t koff = (size_t)kt * 64;
        #pragma unroll
        for (int i = 0; i < 16; i++) {
            int chunk = i * 256 + tid;
            int tensor = chunk >> 10;
            int cid = chunk & 1023;
            int r = cid >> 3;
            int cc = cid & 7;
            uint32_t dst = st + tensor * TILE + SWZ((uint32_t)(r * 128 + cc * 16));
            const __nv_bfloat16* src;
            if (tensor == 0)      src = Ah + (size_t)(bm + r) * K + koff + cc * 8;
            else if (tensor == 1) src = Al + (size_t)(bm + r) * K + koff + cc * 8;
            else if (tensor == 2) src = Bh + (size_t)(bn + r) * K + koff + cc * 8;
            else                  src = Bl + (size_t)(bn + r) * K + koff + cc * 8;
            cpa16(dst, src);
        }
        CP_COMMIT();
    };

    issue_load(0);

    const int a_row = wm + (lane & 15);
    const int a_k8  = (lane >> 4) * 8;
    const int b_row = wn + ((lane >> 4) & 1) * 8 + (lane & 7);
    const int b_k8  = ((lane >> 3) & 1) * 8;

    for (int kt = 0; kt < nk; kt++) {
        const int s = kt & 1;
        if (kt + 1 < nk) { issue_load(kt + 1); CP_WAIT1(); }
        else             { CP_WAIT0(); }
        __syncthreads();

        const uint32_t st  = sb0 + s * (4 * TILE);
        const uint32_t sAh = st;
        const uint32_t sAl = st + TILE;
        const uint32_t sBh = st + 2 * TILE;
        const uint32_t sBl = st + 3 * TILE;

        #pragma unroll
        for (int ks = 0; ks < 4; ks++) {
            const int kb = ks * 16;
            uint32_t aH[4][4], aL[4][4];
            uint32_t bH[8], bL[8];
            #pragma unroll
            for (int mi = 0; mi < 4; mi++) {
                uint32_t off = SWZ((uint32_t)((a_row + mi * 16) * 128 + (kb + a_k8) * 2));
                ldsm_x4(aH[mi], sAh + off);
                ldsm_x4(aL[mi], sAl + off);
            }
            #pragma unroll
            for (int p = 0; p < 2; p++) {
                uint32_t off = SWZ((uint32_t)((b_row + p * 16) * 128 + (kb + b_k8) * 2));
                ldsm_x4(&bH[p * 4], sBh + off);
                ldsm_x4(&bL[p * 4], sBl + off);
            }
            #pragma unroll
            for (int mi = 0; mi < 4; mi++)
                #pragma unroll
                for (int nj = 0; nj < 4; nj++) {
                    mma_bf16(acc[mi][nj], aH[mi], &bH[nj * 2]);
                    mma_bf16(acc[mi][nj], aH[mi], &bL[nj * 2]);
                    mma_bf16(acc[mi][nj], aL[mi], &bH[nj * 2]);
                }
        }
        __syncthreads();
    }

    #pragma unroll
    for (int nj = 0; nj < 4; nj++) {
        const int col = bn + wn + nj * 8 + (lane & 3) * 2;
        float b0 = 0.f, b1 = 0.f;
        if (bias1) { b0 += bias1[col]; b1 += bias1[col + 1]; }
        if (bias2) { b0 += bias2[col]; b1 += bias2[col + 1]; }
        #pragma unroll
        for (int mi = 0; mi < 4; mi++) {
            const int r0 = bm + wm + mi * 16 + (lane >> 2);
            const int r1 = r0 + 8;
            int o0 = permute ? ((r0 & 63) * 32 + (r0 >> 6)) : r0;
            int o1 = permute ? ((r1 & 63) * 32 + (r1 >> 6)) : r1;
            float2 v0 = make_float2(acc[mi][nj][0] + b0, acc[mi][nj][1] + b1);
            float2 v1 = make_float2(acc[mi][nj][2] + b0, acc[mi][nj][3] + b1);
            *(float2*)(C + (size_t)o0 * N + col) = v0;
            *(float2*)(C + (size_t)o1 * N + col) = v1;
        }
    }
}

// ---------------- kernel: linear(2048->512) + batchnorm over batch ------
__global__ void linbn_kernel(const float* __restrict__ img,
                             const float* __restrict__ W,
                             const float* __restrict__ bias,
                             const float* __restrict__ gamma,
                             const float* __restrict__ beta,
                             float* __restrict__ xs)
{
    const int e   = blockIdx.x;
    const int tid = threadIdx.x;
    __shared__ float wrow[IMGF];
    __shared__ float red[8];
    __shared__ float xv[BATCH];

    for (int k = tid; k < IMGF; k += 256) wrow[k] = W[(size_t)e * IMGF + k];
    __syncthreads();

    const int lane = tid & 31, warp = tid >> 5;
    for (int b = 0; b < BATCH; b++) {
        const float* row = img + (size_t)b * IMGF;
        float p = 0.f;
        for (int k = tid; k < IMGF; k += 256) p += row[k] * wrow[k];
        #pragma unroll
        for (int o = 16; o > 0; o >>= 1) p += __shfl_xor_sync(0xffffffffu, p, o);
        if (lane == 0) red[warp] = p;
        __syncthreads();
        if (tid == 0) {
            float s = 0.f;
            #pragma unroll
            for (int w = 0; w < 8; w++) s += red[w];
            xv[b] = s + bias[e];
        }
        __syncthreads();
    }

    if (tid < 32) {
        float x = xv[tid];
        float s = x, q = x * x;
        #pragma unroll
        for (int o = 16; o > 0; o >>= 1) {
            s += __shfl_xor_sync(0xffffffffu, s, o);
            q += __shfl_xor_sync(0xffffffffu, q, o);
        }
        float mu  = s * (1.f / 32.f);
        float var = q * (1.f / 32.f) - mu * mu;
        float inv = rsqrtf(var + 1e-5f);
        float y = gamma[e] * (x - mu) * inv + beta[e];
        xs[((size_t)tid * TSEQ + 0) * EDIM + e] = y;
    }
}

// ---------------- kernel: embedding gather into xs[:,1:,:] --------------
__global__ void gather_kernel(const int* __restrict__ cap,
                              const float* __restrict__ emb,
                              float* __restrict__ xs)
{
    const int t = blockIdx.x + 1;
    const int b = blockIdx.y;
    const int tok = cap[b * TSEQ + (t - 1)];
    const float* src = emb + (size_t)tok * EDIM;
    float* dst = xs + ((size_t)b * TSEQ + t) * EDIM;
    for (int k = threadIdx.x; k < EDIM; k += 128) dst[k] = src[k];
}

// ---------------- kernel: zero h/c state + barrier counter --------------
__global__ void zero_hc(float* __restrict__ h, float* __restrict__ c)
{
    int i = blockIdx.x * 256 + threadIdx.x;
    if (i == 0) g_bar_ctr = 0u;
    if (i < BATCH * HDIM) { h[i] = 0.f; c[i] = 0.f; }
}

// ---------------- persistent LSTM layer (all 64 steps, one launch) ------
// 128 CTAs x 256 thr; CTA owns 8 h-units x 4 gates. Whh slice stays in smem.
__global__ void __launch_bounds__(256, 1)
lstm_persist(const float* __restrict__ pre,   // [T][B][G4]
             const float* __restrict__ Whh,   // [G4][HDIM]
             float* __restrict__ h,
             float* __restrict__ c,
             float* __restrict__ hs_out)
{
    extern __shared__ float sm[];
    float* w_s = sm;                    // [k][32]  k=0..1023
    float* h_s = sm + 32 * 1024;        // [128][36] chunk
    float* g_s = sm + 32 * 1024 + 128 * 36;   // [32][33]

    const int tid = threadIdx.x;
    const int u0  = blockIdx.x * 8;

    // load Whh slice: w_s[k][j] = Whh[jrow(j)][k]
    {
        const int j  = tid >> 3;
        const int kb = (tid & 7) * 128;
        const int wr = (j >> 3) * HDIM + u0 + (j & 7);
        const float* src = Whh + (size_t)wr * HDIM + kb;
        #pragma unroll 4
        for (int i = 0; i < 128; i += 4) {
            float4 v = *(const float4*)(src + i);
            w_s[(kb + i + 0) * 32 + j] = v.x;
            w_s[(kb + i + 1) * 32 + j] = v.y;
            w_s[(kb + i + 2) * 32 + j] = v.z;
            w_s[(kb + i + 3) * 32 + j] = v.w;
        }
    }
    __syncthreads();

    const int jj = tid & 31;
    const int bq = tid >> 5;                 // 0..7 -> 4 batches
    const int b0 = bq * 4;
    const int jrow = (jj >> 3) * HDIM + u0 + (jj & 7);
    unsigned gen = 0;

    for (int t = 0; t < TSEQ; t++) {
        float a0 = 0.f, a1 = 0.f, a2 = 0.f, a3 = 0.f;
        if (t > 0) {
            for (int k0 = 0; k0 < HDIM; k0 += 128) {
                __syncthreads();
                // stage h[32][128] chunk -> h_s[kk][b]
                {
                    const int b  = tid >> 3;
                    const int kq = (tid & 7) * 16;
                    const float* hp = h + (size_t)b * HDIM + k0 + kq;
                    #pragma unroll
                    for (int q = 0; q < 4; q++) {
                        float4 v = *(const float4*)(hp + q * 4);
                        h_s[(kq + q * 4 + 0) * 36 + b] = v.x;
                        h_s[(kq + q * 4 + 1) * 36 + b] = v.y;
                        h_s[(kq + q * 4 + 2) * 36 + b] = v.z;
                        h_s[(kq + q * 4 + 3) * 36 + b] = v.w;
                    }
                }
                __syncthreads();
                #pragma unroll 16
                for (int kk = 0; kk < 128; kk++) {
                    float w = w_s[(k0 + kk) * 32 + jj];
                    const float4 hv = *(const float4*)&h_s[kk * 36 + b0];
                    a0 += w * hv.x; a1 += w * hv.y;
                    a2 += w * hv.z; a3 += w * hv.w;
                }
            }
            __syncthreads();
        }

        // add pre (time-major) and exchange through smem
        {
            const float* pt = pre + (size_t)t * BATCH * G4;
            g_s[jj * 33 + b0 + 0] = a0 + pt[(size_t)(b0 + 0) * G4 + jrow];
            g_s[jj * 33 + b0 + 1] = a1 + pt[(size_t)(b0 + 1) * G4 + jrow];
            g_s[jj * 33 + b0 + 2] = a2 + pt[(size_t)(b0 + 2) * G4 + jrow];
            g_s[jj * 33 + b0 + 3] = a3 + pt[(size_t)(b0 + 3) * G4 + jrow];
        }
        __syncthreads();

        // pointwise: thread -> (unit u, batch b)
        {
            const int u = tid >> 5;
            const int b = tid & 31;
            float gi = g_s[u * 33 + b];
            float gf = g_s[(8 + u) * 33 + b];
            float gg = g_s[(16 + u) * 33 + b];
            float go = g_s[(24 + u) * 33 + b];
            float si = 1.f / (1.f + expf(-gi));
            float sf = 1.f / (1.f + expf(-gf));
            float so = 1.f / (1.f + expf(-go));
            const int ug = u0 + u;
            const size_t ci = (size_t)b * HDIM + ug;
            float cn = sf * c[ci] + si * tanhf(gg);
            float hn = so * tanhf(cn);
            c[ci] = cn;
            h[ci] = hn;
            hs_out[((size_t)b * TSEQ + t) * HDIM + ug] = hn;
        }

        // grid barrier (release/acquire), skip after last step
        if (t + 1 < TSEQ) {
            __syncthreads();
            gen++;
            if (tid == 0) {
                unsigned tgt = gen * NBLK;
                asm volatile("red.release.gpu.global.add.u32 [%0], 1;"
                             :: "l"(&g_bar_ctr) : "memory");
                unsigned v;
                do {
                    asm volatile("ld.acquire.gpu.global.u32 %0, [%1];"
                                 : "=r"(v) : "l"(&g_bar_ctr) : "memory");
                } while (v < tgt);
            }
            __syncthreads();
        }
    }
}

// ---------------- host launch --------------------------------------------
extern "C" void kernel_launch(void* const* d_in, const int* in_sizes, int n_in,
                              void* d_out, int out_size)
{
    const float* image = (const float*)d_in[0];
    const int*   caps  = (const int*)  d_in[1];
    const float* lin_W = (const float*)d_in[2];
    const float* lin_b = (const float*)d_in[3];
    const float* bn_g  = (const float*)d_in[4];
    const float* bn_b  = (const float*)d_in[5];
    const float* emb   = (const float*)d_in[6];
    const float* Wih0  = (const float*)d_in[7];
    const float* Whh0  = (const float*)d_in[8];
    const float* bih0  = (const float*)d_in[9];
    const float* bhh0  = (const float*)d_in[10];
    const float* Wih1  = (const float*)d_in[11];
    const float* Whh1  = (const float*)d_in[12];
    const float* bih1  = (const float*)d_in[13];
    const float* bhh1  = (const float*)d_in[14];
    const float* fc_W  = (const float*)d_in[15];
    const float* fc_b  = (const float*)d_in[16];
    float* out = (float*)d_out;

    float *xs, *pre, *hs0, *hs1, *h, *c;
    __nv_bfloat16 *ah, *al, *w0h, *w0l, *w1h, *w1l, *fh, *fl;
    cudaGetSymbolAddress((void**)&xs,  g_xs);
    cudaGetSymbolAddress((void**)&pre, g_pre);
    cudaGetSymbolAddress((void**)&hs0, g_hs0);
    cudaGetSymbolAddress((void**)&hs1, g_hs1);
    cudaGetSymbolAddress((void**)&h,   g_h);
    cudaGetSymbolAddress((void**)&c,   g_c);
    cudaGetSymbolAddress((void**)&ah,  g_ah);
    cudaGetSymbolAddress((void**)&al,  g_al);
    cudaGetSymbolAddress((void**)&w0h, g_w0h);
    cudaGetSymbolAddress((void**)&w0l, g_w0l);
    cudaGetSymbolAddress((void**)&w1h, g_w1h);
    cudaGetSymbolAddress((void**)&w1l, g_w1l);
    cudaGetSymbolAddress((void**)&fh,  g_fh);
    cudaGetSymbolAddress((void**)&fl,  g_fl);

    static int smem_set = 0;
    const int GEMM_SMEM = 2 * 4 * TILE + 1024;                 // 132KB
    const int LSTM_SMEM = (32 * 1024 + 128 * 36 + 32 * 33) * 4; // ~154KB
    if (!smem_set) {
        cudaFuncSetAttribute(gemm_bf16x3,
                             cudaFuncAttributeMaxDynamicSharedMemorySize, GEMM_SMEM);
        cudaFuncSetAttribute(lstm_persist,
                             cudaFuncAttributeMaxDynamicSharedMemorySize, LSTM_SMEM);
        smem_set = 1;
    }

    // weight conversions
    cvt_hilo<<<(G4 * EDIM / 4 + 255) / 256, 256>>>(Wih0, w0h, w0l, G4 * EDIM);
    cvt_hilo<<<(G4 * HDIM / 4 + 255) / 256, 256>>>(Wih1, w1h, w1l, G4 * HDIM);
    cvt_hilo<<<(VOCAB * HDIM / 4 + 255) / 256, 256>>>(fc_W, fh, fl, VOCAB * HDIM);

    // xs = [bn(linear(image)), emb gather]
    linbn_kernel<<<EDIM, 256>>>(image, lin_W, lin_b, bn_g, bn_b, xs);
    gather_kernel<<<dim3(TSEQ - 1, BATCH), 128>>>(caps, emb, xs);

    // pre0 = xs @ Wih0^T + biases  (time-major output)
    cvt_hilo<<<(MROWS * EDIM / 4 + 255) / 256, 256>>>(xs, ah, al, MROWS * EDIM);
    gemm_bf16x3<<<dim3(MROWS / 128, G4 / 128), 256, GEMM_SMEM>>>(
        ah, al, w0h, w0l, pre, MROWS, G4, EDIM, bih0, bhh0, 1);

    // layer-0 recurrence (persistent)
    zero_hc<<<(BATCH * HDIM + 255) / 256, 256>>>(h, c);
    lstm_persist<<<NBLK, 256, LSTM_SMEM>>>(pre, Whh0, h, c, hs0);

    // pre1 = hs0 @ Wih1^T + biases  (time-major output)
    cvt_hilo<<<(MROWS * HDIM / 4 + 255) / 256, 256>>>(hs0, ah, al, MROWS * HDIM);
    gemm_bf16x3<<<dim3(MROWS / 128, G4 / 128), 256, GEMM_SMEM>>>(
        ah, al, w1h, w1l, pre, MROWS, G4, HDIM, bih1, bhh1, 1);

    // layer-1 recurrence (persistent)
    zero_hc<<<(BATCH * HDIM + 255) / 256, 256>>>(h, c);
    lstm_persist<<<NBLK, 256, LSTM_SMEM>>>(pre, Whh1, h, c, hs1);

    // logits = hs1 @ fc_W^T + fc_b
    cvt_hilo<<<(MROWS * HDIM / 4 + 255) / 256, 256>>>(hs1, ah, al, MROWS * HDIM);
    gemm_bf16x3<<<dim3(MROWS / 128, VOCAB / 128), 256, GEMM_SMEM>>>(
        ah, al, fh, fl, out, MROWS, VOCAB, HDIM, fc_b, nullptr, 0);
}

// round 5
// speedup vs baseline: 3.6597x; 2.0885x over previous
#include <cuda_runtime.h>
#include <cuda_bf16.h>
#include <math.h>
#include <stdint.h>

// Problem dims
#define VOCAB 32000
#define HDIM  1024
#define EDIM  512
#define BATCH 32
#define TSEQ  64
#define IMGF  2048
#define G4    (4*HDIM)          // 4096
#define MROWS (BATCH*TSEQ)      // 2048
#define NBLK  128               // persistent recurrence CTAs

// ---------------- device scratch (no allocation allowed) ----------------
__device__ float g_pre [MROWS * G4];     // time-major: [t][b][G4]
__device__ unsigned g_bar_ctr;

// bf16 hi/lo activations (A operand) + weights
__device__ __nv_bfloat16 g_ah [MROWS * HDIM];
__device__ __nv_bfloat16 g_al [MROWS * HDIM];
__device__ __nv_bfloat16 g_w0h[G4 * EDIM];
__device__ __nv_bfloat16 g_w0l[G4 * EDIM];
__device__ __nv_bfloat16 g_w1h[G4 * HDIM];
__device__ __nv_bfloat16 g_w1l[G4 * HDIM];
__device__ __nv_bfloat16 g_fh [VOCAB * HDIM];
__device__ __nv_bfloat16 g_fl [VOCAB * HDIM];

// ======================= helpers =========================================
__device__ __forceinline__ uint32_t smem_u32(const void* p) {
    uint32_t a;
    asm("{ .reg .u64 t; cvta.to.shared.u64 t, %1; cvt.u32.u64 %0, t; }"
        : "=r"(a) : "l"(p));
    return a;
}
#define SWZ(x) ((x) ^ (((x) >> 3) & 0x70))

__device__ __forceinline__ void cpa16(uint32_t dst, const void* src) {
    asm volatile("cp.async.cg.shared.global [%0], [%1], 16;"
                 :: "r"(dst), "l"(src) : "memory");
}
#define CP_COMMIT() asm volatile("cp.async.commit_group;" ::: "memory")
#define CP_WAIT0()  asm volatile("cp.async.wait_group 0;" ::: "memory")
#define CP_WAIT1()  asm volatile("cp.async.wait_group 1;" ::: "memory")

__device__ __forceinline__ void ldsm_x4(uint32_t* r, uint32_t addr) {
    asm volatile("ldmatrix.sync.aligned.m8n8.x4.shared.b16 {%0,%1,%2,%3}, [%4];"
                 : "=r"(r[0]), "=r"(r[1]), "=r"(r[2]), "=r"(r[3]) : "r"(addr));
}
__device__ __forceinline__ void mma_bf16(float* c, const uint32_t* a, const uint32_t* b) {
    asm volatile(
        "mma.sync.aligned.m16n8k16.row.col.f32.bf16.bf16.f32 "
        "{%0,%1,%2,%3}, {%4,%5,%6,%7}, {%8,%9}, {%0,%1,%2,%3};"
        : "+f"(c[0]), "+f"(c[1]), "+f"(c[2]), "+f"(c[3])
        : "r"(a[0]), "r"(a[1]), "r"(a[2]), "r"(a[3]), "r"(b[0]), "r"(b[1]));
}
__device__ __forceinline__ void split_hilo(float x, __nv_bfloat16& h, __nv_bfloat16& l) {
    h = __float2bfloat16(x);
    l = __float2bfloat16(x - __bfloat162float(h));
}

// ============== fp32 -> bf16 hi/lo split conversion (weights) ============
__global__ void cvt_hilo(const float* __restrict__ x,
                         __nv_bfloat16* __restrict__ hi,
                         __nv_bfloat16* __restrict__ lo, int n)
{
    int i = (blockIdx.x * 256 + threadIdx.x) * 4;
    if (i >= n) return;
    float4 v = *(const float4*)(x + i);
    __nv_bfloat16 h0, h1, h2, h3, l0, l1, l2, l3;
    split_hilo(v.x, h0, l0); split_hilo(v.y, h1, l1);
    split_hilo(v.z, h2, l2); split_hilo(v.w, h3, l3);
    __nv_bfloat162 ph0; ph0.x = h0; ph0.y = h1;
    __nv_bfloat162 ph1; ph1.x = h2; ph1.y = h3;
    __nv_bfloat162 pl0; pl0.x = l0; pl0.y = l1;
    __nv_bfloat162 pl1; pl1.x = l2; pl1.y = l3;
    *(__nv_bfloat162*)(hi + i)     = ph0;
    *(__nv_bfloat162*)(hi + i + 2) = ph1;
    *(__nv_bfloat162*)(lo + i)     = pl0;
    *(__nv_bfloat162*)(lo + i + 2) = pl1;
}

// ============== HMMA bf16x3 GEMM: C = A*B^T + bias =======================
#define TILE 16384
__global__ void __launch_bounds__(256, 1)
gemm_bf16x3(const __nv_bfloat16* __restrict__ Ah, const __nv_bfloat16* __restrict__ Al,
            const __nv_bfloat16* __restrict__ Bh, const __nv_bfloat16* __restrict__ Bl,
            float* __restrict__ C, int M, int N, int K,
            const float* __restrict__ bias1, const float* __restrict__ bias2,
            int permute)
{
    extern __shared__ char dsm[];
    const int tid  = threadIdx.x;
    const int wid  = tid >> 5;
    const int lane = tid & 31;
    const int bm = blockIdx.x * 128;
    const int bn = blockIdx.y * 128;
    const int wm = (wid & 1) * 64;
    const int wn = (wid >> 1) * 32;
    const int nk = K >> 6;

    uint32_t dyn = smem_u32(dsm);
    uint32_t sb0 = (dyn + 1023u) & ~1023u;

    float acc[4][4][4];
    #pragma unroll
    for (int i = 0; i < 4; i++)
        #pragma unroll
        for (int j = 0; j < 4; j++)
            #pragma unroll
            for (int r = 0; r < 4; r++) acc[i][j][r] = 0.f;

    auto issue_load = [&](int kt) {
        const int s = kt & 1;
        const uint32_t st = sb0 + s * (4 * TILE);
        const size_t koff = (size_t)kt * 64;
        #pragma unroll
        for (int i = 0; i < 16; i++) {
            int chunk = i * 256 + tid;
            int tensor = chunk >> 10;
            int cid = chunk & 1023;
            int r = cid >> 3;
            int cc = cid & 7;
            uint32_t dst = st + tensor * TILE + SWZ((uint32_t)(r * 128 + cc * 16));
            const __nv_bfloat16* src;
            if (tensor == 0)      src = Ah + (size_t)(bm + r) * K + koff + cc * 8;
            else if (tensor == 1) src = Al + (size_t)(bm + r) * K + koff + cc * 8;
            else if (tensor == 2) src = Bh + (size_t)(bn + r) * K + koff + cc * 8;
            else                  src = Bl + (size_t)(bn + r) * K + koff + cc * 8;
            cpa16(dst, src);
        }
        CP_COMMIT();
    };

    issue_load(0);

    const int a_row = wm + (lane & 15);
    const int a_k8  = (lane >> 4) * 8;
    const int b_row = wn + ((lane >> 4) & 1) * 8 + (lane & 7);
    const int b_k8  = ((lane >> 3) & 1) * 8;

    for (int kt = 0; kt < nk; kt++) {
        const int s = kt & 1;
        if (kt + 1 < nk) { issue_load(kt + 1); CP_WAIT1(); }
        else             { CP_WAIT0(); }
        __syncthreads();

        const uint32_t st  = sb0 + s * (4 * TILE);
        const uint32_t sAh = st;
        const uint32_t sAl = st + TILE;
        const uint32_t sBh = st + 2 * TILE;
        const uint32_t sBl = st + 3 * TILE;

        #pragma unroll
        for (int ks = 0; ks < 4; ks++) {
            const int kb = ks * 16;
            uint32_t aH[4][4], aL[4][4];
            uint32_t bH[8], bL[8];
            #pragma unroll
            for (int mi = 0; mi < 4; mi++) {
                uint32_t off = SWZ((uint32_t)((a_row + mi * 16) * 128 + (kb + a_k8) * 2));
                ldsm_x4(aH[mi], sAh + off);
                ldsm_x4(aL[mi], sAl + off);
            }
            #pragma unroll
            for (int p = 0; p < 2; p++) {
                uint32_t off = SWZ((uint32_t)((b_row + p * 16) * 128 + (kb + b_k8) * 2));
                ldsm_x4(&bH[p * 4], sBh + off);
                ldsm_x4(&bL[p * 4], sBl + off);
            }
            #pragma unroll
            for (int mi = 0; mi < 4; mi++)
                #pragma unroll
                for (int nj = 0; nj < 4; nj++) {
                    mma_bf16(acc[mi][nj], aH[mi], &bH[nj * 2]);
                    mma_bf16(acc[mi][nj], aH[mi], &bL[nj * 2]);
                    mma_bf16(acc[mi][nj], aL[mi], &bH[nj * 2]);
                }
        }
        __syncthreads();
    }

    #pragma unroll
    for (int nj = 0; nj < 4; nj++) {
        const int col = bn + wn + nj * 8 + (lane & 3) * 2;
        float b0 = 0.f, b1 = 0.f;
        if (bias1) { b0 += bias1[col]; b1 += bias1[col + 1]; }
        if (bias2) { b0 += bias2[col]; b1 += bias2[col + 1]; }
        #pragma unroll
        for (int mi = 0; mi < 4; mi++) {
            const int r0 = bm + wm + mi * 16 + (lane >> 2);
            const int r1 = r0 + 8;
            int o0 = permute ? ((r0 & 63) * 32 + (r0 >> 6)) : r0;
            int o1 = permute ? ((r1 & 63) * 32 + (r1 >> 6)) : r1;
            float2 v0 = make_float2(acc[mi][nj][0] + b0, acc[mi][nj][1] + b1);
            float2 v1 = make_float2(acc[mi][nj][2] + b0, acc[mi][nj][3] + b1);
            *(float2*)(C + (size_t)o0 * N + col) = v0;
            *(float2*)(C + (size_t)o1 * N + col) = v1;
        }
    }
}

// ---------------- linear(2048->512) + batchnorm -> bf16 hi/lo ------------
__global__ void linbn_kernel(const float* __restrict__ img,
                             const float* __restrict__ W,
                             const float* __restrict__ bias,
                             const float* __restrict__ gamma,
                             const float* __restrict__ beta,
                             __nv_bfloat16* __restrict__ ah,
                             __nv_bfloat16* __restrict__ al)
{
    const int e   = blockIdx.x;
    const int tid = threadIdx.x;
    __shared__ float wrow[IMGF];
    __shared__ float xv[BATCH];

    {
        const float* wsrc = W + (size_t)e * IMGF;
        #pragma unroll
        for (int i = 0; i < 2; i++) {
            int k = (tid + i * 256) * 4;
            *(float4*)&wrow[k] = *(const float4*)(wsrc + k);
        }
    }
    __syncthreads();

    const int lane = tid & 31, wid = tid >> 5;
    float a0 = 0.f, a1 = 0.f, a2 = 0.f, a3 = 0.f;
    for (int k = lane; k < IMGF; k += 32) {
        float wv = wrow[k];
        a0 += img[(size_t)(wid +  0) * IMGF + k] * wv;
        a1 += img[(size_t)(wid +  8) * IMGF + k] * wv;
        a2 += img[(size_t)(wid + 16) * IMGF + k] * wv;
        a3 += img[(size_t)(wid + 24) * IMGF + k] * wv;
    }
    #pragma unroll
    for (int o = 16; o > 0; o >>= 1) {
        a0 += __shfl_xor_sync(0xffffffffu, a0, o);
        a1 += __shfl_xor_sync(0xffffffffu, a1, o);
        a2 += __shfl_xor_sync(0xffffffffu, a2, o);
        a3 += __shfl_xor_sync(0xffffffffu, a3, o);
    }
    if (lane == 0) {
        float bb = bias[e];
        xv[wid +  0] = a0 + bb;
        xv[wid +  8] = a1 + bb;
        xv[wid + 16] = a2 + bb;
        xv[wid + 24] = a3 + bb;
    }
    __syncthreads();

    if (tid < 32) {
        float x = xv[tid];
        float s = x, q = x * x;
        #pragma unroll
        for (int o = 16; o > 0; o >>= 1) {
            s += __shfl_xor_sync(0xffffffffu, s, o);
            q += __shfl_xor_sync(0xffffffffu, q, o);
        }
        float mu  = s * (1.f / 32.f);
        float var = q * (1.f / 32.f) - mu * mu;
        float inv = rsqrtf(var + 1e-5f);
        float y = gamma[e] * (x - mu) * inv + beta[e];
        __nv_bfloat16 h, l;
        split_hilo(y, h, l);
        size_t idx = ((size_t)tid * TSEQ + 0) * EDIM + e;
        ah[idx] = h;
        al[idx] = l;
    }
}

// ---------------- embedding gather -> bf16 hi/lo rows t>=1 ---------------
__global__ void gather_kernel(const int* __restrict__ cap,
                              const float* __restrict__ emb,
                              __nv_bfloat16* __restrict__ ah,
                              __nv_bfloat16* __restrict__ al)
{
    const int t = blockIdx.x + 1;
    const int b = blockIdx.y;
    const int tok = cap[b * TSEQ + (t - 1)];
    const int k = threadIdx.x * 4;
    float4 v = *(const float4*)(emb + (size_t)tok * EDIM + k);
    __nv_bfloat16 h0, h1, h2, h3, l0, l1, l2, l3;
    split_hilo(v.x, h0, l0); split_hilo(v.y, h1, l1);
    split_hilo(v.z, h2, l2); split_hilo(v.w, h3, l3);
    __nv_bfloat162 ph0; ph0.x = h0; ph0.y = h1;
    __nv_bfloat162 ph1; ph1.x = h2; ph1.y = h3;
    __nv_bfloat162 pl0; pl0.x = l0; pl0.y = l1;
    __nv_bfloat162 pl1; pl1.x = l2; pl1.y = l3;
    size_t row = ((size_t)b * TSEQ + t) * EDIM + k;
    *(__nv_bfloat162*)(ah + row)     = ph0;
    *(__nv_bfloat162*)(ah + row + 2) = ph1;
    *(__nv_bfloat162*)(al + row)     = pl0;
    *(__nv_bfloat162*)(al + row + 2) = pl1;
}

// ---------------- reset grid-barrier counter ------------------------------
__global__ void reset_bar() { g_bar_ctr = 0u; }

// ---------------- persistent HMMA LSTM layer ------------------------------
// 128 CTAs x 256 thr. CTA owns 32 gate-rows (8 units x 4 gates).
// Whh slice bf16 hi/lo resident in smem; h arrives bf16 hi/lo via ah/al.
__global__ void __launch_bounds__(256, 1)
lstm_persist(const float* __restrict__ pre,   // [T][B][G4]
             const float* __restrict__ Whh,   // [G4][HDIM]
             __nv_bfloat16* __restrict__ ah,  // [b*T+t][HDIM] : h channel + output
             __nv_bfloat16* __restrict__ al)
{
    extern __shared__ char sm_raw[];
    uint32_t raw = smem_u32(sm_raw);
    uint32_t sbase = (raw + 127u) & ~127u;
    char* base = sm_raw + (sbase - raw);
    const uint32_t W_HI = 0;
    const uint32_t W_LO = 65536;
    const uint32_t HBUF = 131072;       // 2 stages x (hi 4096 | lo 4096)
    float* g_s = (float*)(base + 147456);   // [32][33]

    const int tid  = threadIdx.x;
    const int wid  = tid >> 5;
    const int lane = tid & 31;
    const int u0   = blockIdx.x * 8;

    // ---- one-time: convert Whh slice -> smem bf16 hi/lo (swizzled) ----
    #pragma unroll
    for (int i = 0; i < 16; i++) {
        int cell = i * 256 + tid;
        int kt = cell >> 8;
        int r  = (cell >> 3) & 31;
        int cc = cell & 7;
        int jrow = (r >> 3) * HDIM + u0 + (r & 7);
        const float* src = Whh + (size_t)jrow * HDIM + kt * 64 + cc * 8;
        float4 v0 = *(const float4*)src;
        float4 v1 = *(const float4*)(src + 4);
        float f[8] = {v0.x, v0.y, v0.z, v0.w, v1.x, v1.y, v1.z, v1.w};
        uint32_t hi[4], lo[4];
        #pragma unroll
        for (int q = 0; q < 4; q++) {
            __nv_bfloat16 h0, l0, h1, l1;
            split_hilo(f[2*q],   h0, l0);
            split_hilo(f[2*q+1], h1, l1);
            __nv_bfloat162 hp; hp.x = h0; hp.y = h1;
            __nv_bfloat162 lp; lp.x = l0; lp.y = l1;
            hi[q] = *(uint32_t*)&hp;
            lo[q] = *(uint32_t*)&lp;
        }
        uint32_t off = kt * 4096 + SWZ((uint32_t)(r * 128 + cc * 16));
        *(uint4*)(base + W_HI + off) = make_uint4(hi[0], hi[1], hi[2], hi[3]);
        *(uint4*)(base + W_LO + off) = make_uint4(lo[0], lo[1], lo[2], lo[3]);
    }
    __syncthreads();

    // fragment coords
    const int wm = (wid & 1) * 16;          // batches wm..wm+15
    const int wn = (wid >> 1) * 8;          // gate-rows wn..wn+7 (within 32)
    const int a_row = wm + (lane & 15);
    const int a_k8  = (lane >> 4) * 8;      // bytes *2 later
    const int b_row = wn + (lane & 7);
    const int b_ku  = (lane >> 3) & 3;      // 16B unit within 64B pair

    // loader coords (per chunk: 1 hi + 1 lo cp.async per thread)
    const int hr = tid >> 3;                // batch row 0..31
    const int hc = tid & 7;                 // 16B col
    const uint32_t hswz = SWZ((uint32_t)(hr * 128 + hc * 16));

    // pointwise coords
    const int pb = tid >> 3;                // batch
    const int pu = tid & 7;                 // unit within 8
    float c_reg = 0.f;
    unsigned gen = 0;

    for (int t = 0; t < TSEQ; t++) {
        float acc[4] = {0.f, 0.f, 0.f, 0.f};

        if (t > 0) {
            const size_t hrow_base = ((size_t)hr * TSEQ + (t - 1)) * HDIM + hc * 8;
            // prologue: chunks 0,1
            #pragma unroll
            for (int c0 = 0; c0 < 2; c0++) {
                uint32_t dst = sbase + HBUF + c0 * 8192 + hswz;
                cpa16(dst,        ah + hrow_base + c0 * 64);
                cpa16(dst + 4096, al + hrow_base + c0 * 64);
                CP_COMMIT();
            }
            for (int c = 0; c < 16; c++) {
                if (c < 15) { CP_WAIT1(); } else { CP_WAIT0(); }
                __syncthreads();
                const uint32_t hb_hi = sbase + HBUF + (c & 1) * 8192;
                const uint32_t hb_lo = hb_hi + 4096;
                const uint32_t wc = (uint32_t)c * 4096;
                #pragma unroll
                for (int kk2 = 0; kk2 < 2; kk2++) {
                    uint32_t bH4[4], bL4[4];
                    uint32_t boff = wc + SWZ((uint32_t)(b_row * 128 + kk2 * 64 + b_ku * 16));
                    ldsm_x4(bH4, sbase + W_HI + boff);
                    ldsm_x4(bL4, sbase + W_LO + boff);
                    #pragma unroll
                    for (int kh = 0; kh < 2; kh++) {
                        const int ks = kk2 * 2 + kh;
                        uint32_t aH4[4], aL4[4];
                        uint32_t aoff = SWZ((uint32_t)(a_row * 128 + ks * 32 + a_k8 * 2));
                        ldsm_x4(aH4, hb_hi + aoff);
                        ldsm_x4(aL4, hb_lo + aoff);
                        mma_bf16(acc, aH4, &bH4[kh * 2]);
                        mma_bf16(acc, aH4, &bL4[kh * 2]);
                        mma_bf16(acc, aL4, &bH4[kh * 2]);
                    }
                }
                __syncthreads();
                if (c + 2 < 16) {
                    const uint32_t dst = sbase + HBUF + (c & 1) * 8192 + hswz;
                    cpa16(dst,        ah + hrow_base + (c + 2) * 64);
                    cpa16(dst + 4096, al + hrow_base + (c + 2) * 64);
                    CP_COMMIT();
                }
            }
        }

        // epilogue: g = acc + pre[t]
        {
            const float* pt = pre + (size_t)t * BATCH * G4;
            const int jloc = wn + (lane & 3) * 2;          // 0..30 even
            const int jrow = (jloc >> 3) * HDIM + u0 + (jloc & 7);
            const int br = wm + (lane >> 2);
            float2 p0 = *(const float2*)(pt + (size_t)br * G4 + jrow);
            float2 p1 = *(const float2*)(pt + (size_t)(br + 8) * G4 + jrow);
            g_s[jloc * 33 + br]           = acc[0] + p0.x;
            g_s[(jloc + 1) * 33 + br]     = acc[1] + p0.y;
            g_s[jloc * 33 + br + 8]       = acc[2] + p1.x;
            g_s[(jloc + 1) * 33 + br + 8] = acc[3] + p1.y;
        }
        __syncthreads();

        // pointwise
        {
            float gi = g_s[pu * 33 + pb];
            float gf = g_s[(8 + pu) * 33 + pb];
            float gg = g_s[(16 + pu) * 33 + pb];
            float go = g_s[(24 + pu) * 33 + pb];
            float si = 1.f / (1.f + expf(-gi));
            float sf = 1.f / (1.f + expf(-gf));
            float so = 1.f / (1.f + expf(-go));
            c_reg = sf * c_reg + si * tanhf(gg);
            float hn = so * tanhf(c_reg);
            __nv_bfloat16 hh, hl;
            split_hilo(hn, hh, hl);
            size_t orow = ((size_t)pb * TSEQ + t) * HDIM + u0 + pu;
            ah[orow] = hh;
            al[orow] = hl;
        }
        __syncthreads();

        if (t + 1 < TSEQ) {
            gen++;
            if (tid == 0) {
                asm volatile("membar.gl;" ::: "memory");
                asm volatile("red.release.gpu.global.add.u32 [%0], 1;"
                             :: "l"(&g_bar_ctr) : "memory");
                unsigned tgt = gen * NBLK, v;
                do {
                    asm volatile("ld.acquire.gpu.global.u32 %0, [%1];"
                                 : "=r"(v) : "l"(&g_bar_ctr) : "memory");
                } while (v < tgt);
            }
            __syncthreads();
        }
    }
}

// ---------------- host launch --------------------------------------------
extern "C" void kernel_launch(void* const* d_in, const int* in_sizes, int n_in,
                              void* d_out, int out_size)
{
    const float* image = (const float*)d_in[0];
    const int*   caps  = (const int*)  d_in[1];
    const float* lin_W = (const float*)d_in[2];
    const float* lin_b = (const float*)d_in[3];
    const float* bn_g  = (const float*)d_in[4];
    const float* bn_b  = (const float*)d_in[5];
    const float* emb   = (const float*)d_in[6];
    const float* Wih0  = (const float*)d_in[7];
    const float* Whh0  = (const float*)d_in[8];
    const float* bih0  = (const float*)d_in[9];
    const float* bhh0  = (const float*)d_in[10];
    const float* Wih1  = (const float*)d_in[11];
    const float* Whh1  = (const float*)d_in[12];
    const float* bih1  = (const float*)d_in[13];
    const float* bhh1  = (const float*)d_in[14];
    const float* fc_W  = (const float*)d_in[15];
    const float* fc_b  = (const float*)d_in[16];
    float* out = (float*)d_out;

    float *pre;
    __nv_bfloat16 *ah, *al, *w0h, *w0l, *w1h, *w1l, *fh, *fl;
    cudaGetSymbolAddress((void**)&pre, g_pre);
    cudaGetSymbolAddress((void**)&ah,  g_ah);
    cudaGetSymbolAddress((void**)&al,  g_al);
    cudaGetSymbolAddress((void**)&w0h, g_w0h);
    cudaGetSymbolAddress((void**)&w0l, g_w0l);
    cudaGetSymbolAddress((void**)&w1h, g_w1h);
    cudaGetSymbolAddress((void**)&w1l, g_w1l);
    cudaGetSymbolAddress((void**)&fh,  g_fh);
    cudaGetSymbolAddress((void**)&fl,  g_fl);

    static int smem_set = 0;
    const int GEMM_SMEM = 2 * 4 * TILE + 1024;              // 132KB
    const int LSTM_SMEM = 147456 + 32 * 33 * 4 + 256;       // ~152KB
    if (!smem_set) {
        cudaFuncSetAttribute(gemm_bf16x3,
                             cudaFuncAttributeMaxDynamicSharedMemorySize, GEMM_SMEM);
        cudaFuncSetAttribute(lstm_persist,
                             cudaFuncAttributeMaxDynamicSharedMemorySize, LSTM_SMEM);
        smem_set = 1;
    }

    // weight conversions
    cvt_hilo<<<(G4 * EDIM / 4 + 255) / 256, 256>>>(Wih0, w0h, w0l, G4 * EDIM);
    cvt_hilo<<<(G4 * HDIM / 4 + 255) / 256, 256>>>(Wih1, w1h, w1l, G4 * HDIM);
    cvt_hilo<<<(VOCAB * HDIM / 4 + 255) / 256, 256>>>(fc_W, fh, fl, VOCAB * HDIM);

    // inputs -> ah/al rows (K=EDIM layout)
    linbn_kernel<<<EDIM, 256>>>(image, lin_W, lin_b, bn_g, bn_b, ah, al);
    gather_kernel<<<dim3(TSEQ - 1, BATCH), 128>>>(caps, emb, ah, al);

    // pre0 = xs @ Wih0^T + biases (time-major out)
    gemm_bf16x3<<<dim3(MROWS / 128, G4 / 128), 256, GEMM_SMEM>>>(
        ah, al, w0h, w0l, pre, MROWS, G4, EDIM, bih0, bhh0, 1);

    // layer-0 recurrence (persistent, HMMA); writes ah/al (K=HDIM layout)
    reset_bar<<<1, 1>>>();
    lstm_persist<<<NBLK, 256, LSTM_SMEM>>>(pre, Whh0, ah, al);

    // pre1 = hs0 @ Wih1^T + biases (time-major out)
    gemm_bf16x3<<<dim3(MROWS / 128, G4 / 128), 256, GEMM_SMEM>>>(
        ah, al, w1h, w1l, pre, MROWS, G4, HDIM, bih1, bhh1, 1);

    // layer-1 recurrence
    reset_bar<<<1, 1>>>();
    lstm_persist<<<NBLK, 256, LSTM_SMEM>>>(pre, Whh1, ah, al);

    // logits = hs1 @ fc_W^T + fc_b
    gemm_bf16x3<<<dim3(MROWS / 128, VOCAB / 128), 256, GEMM_SMEM>>>(
        ah, al, fh, fl, out, MROWS, VOCAB, HDIM, fc_b, nullptr, 0);
}

// round 6
// speedup vs baseline: 3.8194x; 1.0436x over previous
#include <cuda_runtime.h>
#include <cuda_bf16.h>
#include <math.h>
#include <stdint.h>

// Problem dims
#define VOCAB 32000
#define HDIM  1024
#define EDIM  512
#define BATCH 32
#define TSEQ  64
#define IMGF  2048
#define G4    (4*HDIM)          // 4096
#define MROWS (BATCH*TSEQ)      // 2048
#define NBLK  128               // persistent recurrence CTAs

// ---------------- device scratch (no allocation allowed) ----------------
__device__ float g_pre [MROWS * G4];     // time-major: [t][b][G4]
__device__ unsigned g_bar_ctr;

// bf16 hi/lo activations (A operand) + weights
__device__ __nv_bfloat16 g_ah [MROWS * HDIM];
__device__ __nv_bfloat16 g_al [MROWS * HDIM];
__device__ __nv_bfloat16 g_w0h[G4 * EDIM];
__device__ __nv_bfloat16 g_w0l[G4 * EDIM];
__device__ __nv_bfloat16 g_w1h[G4 * HDIM];
__device__ __nv_bfloat16 g_w1l[G4 * HDIM];
__device__ __nv_bfloat16 g_fh [VOCAB * HDIM];
__device__ __nv_bfloat16 g_fl [VOCAB * HDIM];

// ======================= helpers =========================================
__device__ __forceinline__ uint32_t smem_u32(const void* p) {
    uint32_t a;
    asm("{ .reg .u64 t; cvta.to.shared.u64 t, %1; cvt.u32.u64 %0, t; }"
        : "=r"(a) : "l"(p));
    return a;
}
#define SWZ(x) ((x) ^ (((x) >> 3) & 0x70))

__device__ __forceinline__ void cpa16(uint32_t dst, const void* src) {
    asm volatile("cp.async.cg.shared.global [%0], [%1], 16;"
                 :: "r"(dst), "l"(src) : "memory");
}
#define CP_COMMIT() asm volatile("cp.async.commit_group;" ::: "memory")
#define CP_WAIT0()  asm volatile("cp.async.wait_group 0;" ::: "memory")
#define CP_WAIT1()  asm volatile("cp.async.wait_group 1;" ::: "memory")

__device__ __forceinline__ void ldsm_x4(uint32_t* r, uint32_t addr) {
    asm volatile("ldmatrix.sync.aligned.m8n8.x4.shared.b16 {%0,%1,%2,%3}, [%4];"
                 : "=r"(r[0]), "=r"(r[1]), "=r"(r[2]), "=r"(r[3]) : "r"(addr));
}
__device__ __forceinline__ void mma_bf16(float* c, const uint32_t* a, const uint32_t* b) {
    asm volatile(
        "mma.sync.aligned.m16n8k16.row.col.f32.bf16.bf16.f32 "
        "{%0,%1,%2,%3}, {%4,%5,%6,%7}, {%8,%9}, {%0,%1,%2,%3};"
        : "+f"(c[0]), "+f"(c[1]), "+f"(c[2]), "+f"(c[3])
        : "r"(a[0]), "r"(a[1]), "r"(a[2]), "r"(a[3]), "r"(b[0]), "r"(b[1]));
}
__device__ __forceinline__ void split_hilo(float x, __nv_bfloat16& h, __nv_bfloat16& l) {
    h = __float2bfloat16(x);
    l = __float2bfloat16(x - __bfloat162float(h));
}

// ============== fp32 -> bf16 hi/lo split conversion (weights) ============
__global__ void cvt_hilo(const float* __restrict__ x,
                         __nv_bfloat16* __restrict__ hi,
                         __nv_bfloat16* __restrict__ lo, int n)
{
    int i = (blockIdx.x * 256 + threadIdx.x) * 4;
    if (i >= n) return;
    float4 v = *(const float4*)(x + i);
    __nv_bfloat16 h0, h1, h2, h3, l0, l1, l2, l3;
    split_hilo(v.x, h0, l0); split_hilo(v.y, h1, l1);
    split_hilo(v.z, h2, l2); split_hilo(v.w, h3, l3);
    __nv_bfloat162 ph0; ph0.x = h0; ph0.y = h1;
    __nv_bfloat162 ph1; ph1.x = h2; ph1.y = h3;
    __nv_bfloat162 pl0; pl0.x = l0; pl0.y = l1;
    __nv_bfloat162 pl1; pl1.x = l2; pl1.y = l3;
    *(__nv_bfloat162*)(hi + i)     = ph0;
    *(__nv_bfloat162*)(hi + i + 2) = ph1;
    *(__nv_bfloat162*)(lo + i)     = pl0;
    *(__nv_bfloat162*)(lo + i + 2) = pl1;
}

// ============== HMMA bf16x3 GEMM: C = A*B^T + bias =======================
// CTA tile 128M x 256N, warp tile 64x64, K-chunk 64. N%256==0, M%128==0.
#define A_T   16384                 // 128 rows x 128B
#define B_T   32768                 // 256 rows x 128B
#define STAGE (2*A_T + 2*B_T)       // 96KB
__global__ void __launch_bounds__(256, 1)
gemm_bf16x3(const __nv_bfloat16* __restrict__ Ah, const __nv_bfloat16* __restrict__ Al,
            const __nv_bfloat16* __restrict__ Bh, const __nv_bfloat16* __restrict__ Bl,
            float* __restrict__ C, int M, int N, int K,
            const float* __restrict__ bias1, const float* __restrict__ bias2,
            int permute)
{
    extern __shared__ char dsm[];
    const int tid  = threadIdx.x;
    const int wid  = tid >> 5;
    const int lane = tid & 31;
    const int bm = blockIdx.x * 128;
    const int bn = blockIdx.y * 256;
    const int wm = (wid & 1) * 64;
    const int wn = (wid >> 1) * 64;
    const int nk = K >> 6;

    // fold in the grid-barrier reset for the following lstm launch
    if (blockIdx.x == 0 && blockIdx.y == 0 && tid == 0) g_bar_ctr = 0u;

    uint32_t dyn = smem_u32(dsm);
    uint32_t sb0 = (dyn + 1023u) & ~1023u;

    float acc[4][8][4];
    #pragma unroll
    for (int i = 0; i < 4; i++)
        #pragma unroll
        for (int j = 0; j < 8; j++)
            #pragma unroll
            for (int r = 0; r < 4; r++) acc[i][j][r] = 0.f;

    auto issue_load = [&](int kt) {
        const uint32_t st = sb0 + (kt & 1) * STAGE;
        const size_t koff = (size_t)kt * 64;
        #pragma unroll
        for (int i = 0; i < 8; i++) {           // A: hi | lo
            int id = i * 256 + tid;
            int tensor = id >> 10;
            int cid = id & 1023;
            int r = cid >> 3, c = cid & 7;
            uint32_t dst = st + tensor * A_T + SWZ((uint32_t)(r * 128 + c * 16));
            const __nv_bfloat16* src = (tensor == 0 ? Ah : Al)
                                     + (size_t)(bm + r) * K + koff + c * 8;
            cpa16(dst, src);
        }
        #pragma unroll
        for (int i = 0; i < 16; i++) {          // B: hi | lo
            int id = i * 256 + tid;
            int tensor = id >> 11;
            int cid = id & 2047;
            int r = cid >> 3, c = cid & 7;
            uint32_t dst = st + 2 * A_T + tensor * B_T + SWZ((uint32_t)(r * 128 + c * 16));
            const __nv_bfloat16* src = (tensor == 0 ? Bh : Bl)
                                     + (size_t)(bn + r) * K + koff + c * 8;
            cpa16(dst, src);
        }
        CP_COMMIT();
    };

    issue_load(0);

    const int a_row = wm + (lane & 15);
    const int a_k8  = (lane >> 4) * 8;
    const int b_row = wn + ((lane >> 4) & 1) * 8 + (lane & 7);
    const int b_k8  = ((lane >> 3) & 1) * 8;

    for (int kt = 0; kt < nk; kt++) {
        if (kt + 1 < nk) { issue_load(kt + 1); CP_WAIT1(); }
        else             { CP_WAIT0(); }
        __syncthreads();

        const uint32_t st  = sb0 + (kt & 1) * STAGE;
        const uint32_t sAh = st;
        const uint32_t sAl = st + A_T;
        const uint32_t sBh = st + 2 * A_T;
        const uint32_t sBl = st + 2 * A_T + B_T;

        #pragma unroll
        for (int ks = 0; ks < 4; ks++) {
            const int kb = ks * 16;
            uint32_t aH[4][4], aL[4][4];
            #pragma unroll
            for (int mi = 0; mi < 4; mi++) {
                uint32_t off = SWZ((uint32_t)((a_row + mi * 16) * 128 + (kb + a_k8) * 2));
                ldsm_x4(aH[mi], sAh + off);
                ldsm_x4(aL[mi], sAl + off);
            }
            #pragma unroll
            for (int half = 0; half < 2; half++) {
                uint32_t bH[8], bL[8];
                #pragma unroll
                for (int p = 0; p < 2; p++) {
                    uint32_t off = SWZ((uint32_t)((b_row + half * 32 + p * 16) * 128
                                                  + (kb + b_k8) * 2));
                    ldsm_x4(&bH[p * 4], sBh + off);
                    ldsm_x4(&bL[p * 4], sBl + off);
                }
                #pragma unroll
                for (int mi = 0; mi < 4; mi++)
                    #pragma unroll
                    for (int j = 0; j < 4; j++) {
                        float* a4 = acc[mi][half * 4 + j];
                        mma_bf16(a4, aH[mi], &bH[j * 2]);
                        mma_bf16(a4, aH[mi], &bL[j * 2]);
                        mma_bf16(a4, aL[mi], &bH[j * 2]);
                    }
            }
        }
        __syncthreads();
    }

    #pragma unroll
    for (int nj = 0; nj < 8; nj++) {
        const int col = bn + wn + nj * 8 + (lane & 3) * 2;
        float b0 = 0.f, b1 = 0.f;
        if (bias1) { b0 += bias1[col]; b1 += bias1[col + 1]; }
        if (bias2) { b0 += bias2[col]; b1 += bias2[col + 1]; }
        #pragma unroll
        for (int mi = 0; mi < 4; mi++) {
            const int r0 = bm + wm + mi * 16 + (lane >> 2);
            const int r1 = r0 + 8;
            int o0 = permute ? ((r0 & 63) * 32 + (r0 >> 6)) : r0;
            int o1 = permute ? ((r1 & 63) * 32 + (r1 >> 6)) : r1;
            float2 v0 = make_float2(acc[mi][nj][0] + b0, acc[mi][nj][1] + b1);
            float2 v1 = make_float2(acc[mi][nj][2] + b0, acc[mi][nj][3] + b1);
            *(float2*)(C + (size_t)o0 * N + col) = v0;
            *(float2*)(C + (size_t)o1 * N + col) = v1;
        }
    }
}

// ---------------- linear(2048->512) + batchnorm -> bf16 hi/lo ------------
__global__ void linbn_kernel(const float* __restrict__ img,
                             const float* __restrict__ W,
                             const float* __restrict__ bias,
                             const float* __restrict__ gamma,
                             const float* __restrict__ beta,
                             __nv_bfloat16* __restrict__ ah,
                             __nv_bfloat16* __restrict__ al)
{
    const int e   = blockIdx.x;
    const int tid = threadIdx.x;
    __shared__ float wrow[IMGF];
    __shared__ float xv[BATCH];

    {
        const float* wsrc = W + (size_t)e * IMGF;
        #pragma unroll
        for (int i = 0; i < 2; i++) {
            int k = (tid + i * 256) * 4;
            *(float4*)&wrow[k] = *(const float4*)(wsrc + k);
        }
    }
    __syncthreads();

    const int lane = tid & 31, wid = tid >> 5;
    float a0 = 0.f, a1 = 0.f, a2 = 0.f, a3 = 0.f;
    for (int k = lane; k < IMGF; k += 32) {
        float wv = wrow[k];
        a0 += img[(size_t)(wid +  0) * IMGF + k] * wv;
        a1 += img[(size_t)(wid +  8) * IMGF + k] * wv;
        a2 += img[(size_t)(wid + 16) * IMGF + k] * wv;
        a3 += img[(size_t)(wid + 24) * IMGF + k] * wv;
    }
    #pragma unroll
    for (int o = 16; o > 0; o >>= 1) {
        a0 += __shfl_xor_sync(0xffffffffu, a0, o);
        a1 += __shfl_xor_sync(0xffffffffu, a1, o);
        a2 += __shfl_xor_sync(0xffffffffu, a2, o);
        a3 += __shfl_xor_sync(0xffffffffu, a3, o);
    }
    if (lane == 0) {
        float bb = bias[e];
        xv[wid +  0] = a0 + bb;
        xv[wid +  8] = a1 + bb;
        xv[wid + 16] = a2 + bb;
        xv[wid + 24] = a3 + bb;
    }
    __syncthreads();

    if (tid < 32) {
        float x = xv[tid];
        float s = x, q = x * x;
        #pragma unroll
        for (int o = 16; o > 0; o >>= 1) {
            s += __shfl_xor_sync(0xffffffffu, s, o);
            q += __shfl_xor_sync(0xffffffffu, q, o);
        }
        float mu  = s * (1.f / 32.f);
        float var = q * (1.f / 32.f) - mu * mu;
        float inv = rsqrtf(var + 1e-5f);
        float y = gamma[e] * (x - mu) * inv + beta[e];
        __nv_bfloat16 h, l;
        split_hilo(y, h, l);
        size_t idx = ((size_t)tid * TSEQ + 0) * EDIM + e;
        ah[idx] = h;
        al[idx] = l;
    }
}

// ---------------- embedding gather -> bf16 hi/lo rows t>=1 ---------------
__global__ void gather_kernel(const int* __restrict__ cap,
                              const float* __restrict__ emb,
                              __nv_bfloat16* __restrict__ ah,
                              __nv_bfloat16* __restrict__ al)
{
    const int t = blockIdx.x + 1;
    const int b = blockIdx.y;
    const int tok = cap[b * TSEQ + (t - 1)];
    const int k = threadIdx.x * 4;
    float4 v = *(const float4*)(emb + (size_t)tok * EDIM + k);
    __nv_bfloat16 h0, h1, h2, h3, l0, l1, l2, l3;
    split_hilo(v.x, h0, l0); split_hilo(v.y, h1, l1);
    split_hilo(v.z, h2, l2); split_hilo(v.w, h3, l3);
    __nv_bfloat162 ph0; ph0.x = h0; ph0.y = h1;
    __nv_bfloat162 ph1; ph1.x = h2; ph1.y = h3;
    __nv_bfloat162 pl0; pl0.x = l0; pl0.y = l1;
    __nv_bfloat162 pl1; pl1.x = l2; pl1.y = l3;
    size_t row = ((size_t)b * TSEQ + t) * EDIM + k;
    *(__nv_bfloat162*)(ah + row)     = ph0;
    *(__nv_bfloat162*)(ah + row + 2) = ph1;
    *(__nv_bfloat162*)(al + row)     = pl0;
    *(__nv_bfloat162*)(al + row + 2) = pl1;
}

// ---------------- persistent HMMA LSTM layer ------------------------------
// 128 CTAs x 256 thr. CTA owns 32 gate-rows (8 units x 4 gates).
// Whh slice bf16 hi/lo in smem; h arrives bf16 hi/lo via ah/al.
// Per-step h staged in 8 chunks of k=128 (2 swizzled 64-k subtiles each).
__global__ void __launch_bounds__(256, 1)
lstm_persist(const float* __restrict__ pre,   // [T][B][G4]
             const float* __restrict__ Whh,   // [G4][HDIM]
             __nv_bfloat16* __restrict__ ah,  // [b*T+t][HDIM]
             __nv_bfloat16* __restrict__ al)
{
    extern __shared__ char sm_raw[];
    uint32_t raw = smem_u32(sm_raw);
    uint32_t sbase = (raw + 127u) & ~127u;
    char* base = sm_raw + (sbase - raw);
    const uint32_t W_HI = 0;
    const uint32_t W_LO = 65536;
    const uint32_t HBUF = 131072;            // 2 stages x 16KB
    float* g_s = (float*)(base + 163840);    // [32][33]

    const int tid  = threadIdx.x;
    const int wid  = tid >> 5;
    const int lane = tid & 31;
    const int u0   = blockIdx.x * 8;

    // one-time: convert Whh slice -> smem bf16 hi/lo (swizzled, 64k tiles)
    #pragma unroll
    for (int i = 0; i < 16; i++) {
        int cell = i * 256 + tid;
        int kt = cell >> 8;
        int r  = (cell >> 3) & 31;
        int cc = cell & 7;
        int jrow = (r >> 3) * HDIM + u0 + (r & 7);
        const float* src = Whh + (size_t)jrow * HDIM + kt * 64 + cc * 8;
        float4 v0 = *(const float4*)src;
        float4 v1 = *(const float4*)(src + 4);
        float f[8] = {v0.x, v0.y, v0.z, v0.w, v1.x, v1.y, v1.z, v1.w};
        uint32_t hi[4], lo[4];
        #pragma unroll
        for (int q = 0; q < 4; q++) {
            __nv_bfloat16 h0, l0, h1, l1;
            split_hilo(f[2*q],   h0, l0);
            split_hilo(f[2*q+1], h1, l1);
            __nv_bfloat162 hp; hp.x = h0; hp.y = h1;
            __nv_bfloat162 lp; lp.x = l0; lp.y = l1;
            hi[q] = *(uint32_t*)&hp;
            lo[q] = *(uint32_t*)&lp;
        }
        uint32_t off = kt * 4096 + SWZ((uint32_t)(r * 128 + cc * 16));
        *(uint4*)(base + W_HI + off) = make_uint4(hi[0], hi[1], hi[2], hi[3]);
        *(uint4*)(base + W_LO + off) = make_uint4(lo[0], lo[1], lo[2], lo[3]);
    }
    __syncthreads();

    const int wm = (wid & 1) * 16;
    const int wn = (wid >> 1) * 8;
    const int a_row = wm + (lane & 15);
    const int a_k8  = (lane >> 4) * 8;
    const int b_row = wn + (lane & 7);
    const int b_ku  = (lane >> 3) & 3;

    const int hr = tid >> 3;
    const int hc = tid & 7;
    const uint32_t hswz = SWZ((uint32_t)(hr * 128 + hc * 16));

    const int pb = tid >> 3;
    const int pu = tid & 7;
    float c_reg = 0.f;
    unsigned gen = 0;

    for (int t = 0; t < TSEQ; t++) {
        float acc[4] = {0.f, 0.f, 0.f, 0.f};

        if (t > 0) {
            const size_t hrow_base = ((size_t)hr * TSEQ + (t - 1)) * HDIM + hc * 8;
            // issue chunk c: 4 cpa16 (hi sub0/sub1, lo sub0/sub1)
            auto issue_chunk = [&](int c) {
                const uint32_t d = sbase + HBUF + (c & 1) * 16384 + hswz;
                const size_t g = hrow_base + (size_t)c * 128;
                cpa16(d,         ah + g);
                cpa16(d + 4096,  ah + g + 64);
                cpa16(d + 8192,  al + g);
                cpa16(d + 12288, al + g + 64);
                CP_COMMIT();
            };
            issue_chunk(0);
            issue_chunk(1);
            for (int c = 0; c < 8; c++) {
                if (c < 7) { CP_WAIT1(); } else { CP_WAIT0(); }
                __syncthreads();
                const uint32_t stg = sbase + HBUF + (c & 1) * 16384;
                #pragma unroll
                for (int sub = 0; sub < 2; sub++) {
                    const uint32_t wc = (uint32_t)(2 * c + sub) * 4096;
                    const uint32_t hb_hi = stg + sub * 4096;
                    const uint32_t hb_lo = stg + 8192 + sub * 4096;
                    #pragma unroll
                    for (int kk2 = 0; kk2 < 2; kk2++) {
                        uint32_t bH4[4], bL4[4];
                        uint32_t boff = wc + SWZ((uint32_t)(b_row * 128 + kk2 * 64 + b_ku * 16));
                        ldsm_x4(bH4, sbase + W_HI + boff);
                        ldsm_x4(bL4, sbase + W_LO + boff);
                        #pragma unroll
                        for (int kh = 0; kh < 2; kh++) {
                            const int ks = kk2 * 2 + kh;
                            uint32_t aH4[4], aL4[4];
                            uint32_t aoff = SWZ((uint32_t)(a_row * 128 + ks * 32 + a_k8 * 2));
                            ldsm_x4(aH4, hb_hi + aoff);
                            ldsm_x4(aL4, hb_lo + aoff);
                            mma_bf16(acc, aH4, &bH4[kh * 2]);
                            mma_bf16(acc, aH4, &bL4[kh * 2]);
                            mma_bf16(acc, aL4, &bH4[kh * 2]);
                        }
                    }
                }
                __syncthreads();
                if (c + 2 < 8) issue_chunk(c + 2);
            }
        }

        // epilogue: g = acc + pre[t]
        {
            const float* pt = pre + (size_t)t * BATCH * G4;
            const int jloc = wn + (lane & 3) * 2;
            const int jrow = (jloc >> 3) * HDIM + u0 + (jloc & 7);
            const int br = wm + (lane >> 2);
            float2 p0 = *(const float2*)(pt + (size_t)br * G4 + jrow);
            float2 p1 = *(const float2*)(pt + (size_t)(br + 8) * G4 + jrow);
            g_s[jloc * 33 + br]           = acc[0] + p0.x;
            g_s[(jloc + 1) * 33 + br]     = acc[1] + p0.y;
            g_s[jloc * 33 + br + 8]       = acc[2] + p1.x;
            g_s[(jloc + 1) * 33 + br + 8] = acc[3] + p1.y;
        }
        __syncthreads();

        // pointwise
        {
            float gi = g_s[pu * 33 + pb];
            float gf = g_s[(8 + pu) * 33 + pb];
            float gg = g_s[(16 + pu) * 33 + pb];
            float go = g_s[(24 + pu) * 33 + pb];
            float si = 1.f / (1.f + expf(-gi));
            float sf = 1.f / (1.f + expf(-gf));
            float so = 1.f / (1.f + expf(-go));
            c_reg = sf * c_reg + si * tanhf(gg);
            float hn = so * tanhf(c_reg);
            __nv_bfloat16 hh, hl;
            split_hilo(hn, hh, hl);
            size_t orow = ((size_t)pb * TSEQ + t) * HDIM + u0 + pu;
            ah[orow] = hh;
            al[orow] = hl;
        }
        __syncthreads();

        if (t + 1 < TSEQ) {
            gen++;
            if (tid == 0) {
                asm volatile("membar.gl;" ::: "memory");
                asm volatile("red.release.gpu.global.add.u32 [%0], 1;"
                             :: "l"(&g_bar_ctr) : "memory");
                unsigned tgt = gen * NBLK, v;
                do {
                    asm volatile("ld.acquire.gpu.global.u32 %0, [%1];"
                                 : "=r"(v) : "l"(&g_bar_ctr) : "memory");
                } while (v < tgt);
            }
            __syncthreads();
        }
    }
}

// ---------------- host launch --------------------------------------------
extern "C" void kernel_launch(void* const* d_in, const int* in_sizes, int n_in,
                              void* d_out, int out_size)
{
    const float* image = (const float*)d_in[0];
    const int*   caps  = (const int*)  d_in[1];
    const float* lin_W = (const float*)d_in[2];
    const float* lin_b = (const float*)d_in[3];
    const float* bn_g  = (const float*)d_in[4];
    const float* bn_b  = (const float*)d_in[5];
    const float* emb   = (const float*)d_in[6];
    const float* Wih0  = (const float*)d_in[7];
    const float* Whh0  = (const float*)d_in[8];
    const float* bih0  = (const float*)d_in[9];
    const float* bhh0  = (const float*)d_in[10];
    const float* Wih1  = (const float*)d_in[11];
    const float* Whh1  = (const float*)d_in[12];
    const float* bih1  = (const float*)d_in[13];
    const float* bhh1  = (const float*)d_in[14];
    const float* fc_W  = (const float*)d_in[15];
    const float* fc_b  = (const float*)d_in[16];
    float* out = (float*)d_out;

    float *pre;
    __nv_bfloat16 *ah, *al, *w0h, *w0l, *w1h, *w1l, *fh, *fl;
    cudaGetSymbolAddress((void**)&pre, g_pre);
    cudaGetSymbolAddress((void**)&ah,  g_ah);
    cudaGetSymbolAddress((void**)&al,  g_al);
    cudaGetSymbolAddress((void**)&w0h, g_w0h);
    cudaGetSymbolAddress((void**)&w0l, g_w0l);
    cudaGetSymbolAddress((void**)&w1h, g_w1h);
    cudaGetSymbolAddress((void**)&w1l, g_w1l);
    cudaGetSymbolAddress((void**)&fh,  g_fh);
    cudaGetSymbolAddress((void**)&fl,  g_fl);

    static int smem_set = 0;
    const int GEMM_SMEM = 2 * STAGE + 1024;                  // ~193KB
    const int LSTM_SMEM = 163840 + 32 * 33 * 4 + 256;        // ~168KB
    if (!smem_set) {
        cudaFuncSetAttribute(gemm_bf16x3,
                             cudaFuncAttributeMaxDynamicSharedMemorySize, GEMM_SMEM);
        cudaFuncSetAttribute(lstm_persist,
                             cudaFuncAttributeMaxDynamicSharedMemorySize, LSTM_SMEM);
        smem_set = 1;
    }

    // inputs -> ah/al rows (K=EDIM layout)
    linbn_kernel<<<EDIM, 256>>>(image, lin_W, lin_b, bn_g, bn_b, ah, al);
    gather_kernel<<<dim3(TSEQ - 1, BATCH), 128>>>(caps, emb, ah, al);

    // layer-0 input weights, then pre0 GEMM (4th launch -> ncu window)
    cvt_hilo<<<(G4 * EDIM / 4 + 255) / 256, 256>>>(Wih0, w0h, w0l, G4 * EDIM);
    gemm_bf16x3<<<dim3(MROWS / 128, G4 / 256), 256, GEMM_SMEM>>>(
        ah, al, w0h, w0l, pre, MROWS, G4, EDIM, bih0, bhh0, 1);

    // remaining weight conversions
    cvt_hilo<<<(G4 * HDIM / 4 + 255) / 256, 256>>>(Wih1, w1h, w1l, G4 * HDIM);
    cvt_hilo<<<(VOCAB * HDIM / 4 + 255) / 256, 256>>>(fc_W, fh, fl, VOCAB * HDIM);

    // layer-0 recurrence (bar reset folded into gemm above)
    lstm_persist<<<NBLK, 256, LSTM_SMEM>>>(pre, Whh0, ah, al);

    // pre1 = hs0 @ Wih1^T + biases (resets bar for lstm1)
    gemm_bf16x3<<<dim3(MROWS / 128, G4 / 256), 256, GEMM_SMEM>>>(
        ah, al, w1h, w1l, pre, MROWS, G4, HDIM, bih1, bhh1, 1);

    // layer-1 recurrence
    lstm_persist<<<NBLK, 256, LSTM_SMEM>>>(pre, Whh1, ah, al);

    // logits = hs1 @ fc_W^T + fc_b
    gemm_bf16x3<<<dim3(MROWS / 128, VOCAB / 256), 256, GEMM_SMEM>>>(
        ah, al, fh, fl, out, MROWS, VOCAB, HDIM, fc_b, nullptr, 0);
}

// round 7
// speedup vs baseline: 3.8571x; 1.0099x over previous
#include <cuda_runtime.h>
#include <cuda_bf16.h>
#include <math.h>
#include <stdint.h>

// Problem dims
#define VOCAB 32000
#define HDIM  1024
#define EDIM  512
#define BATCH 32
#define TSEQ  64
#define IMGF  2048
#define G4    (4*HDIM)          // 4096
#define MROWS (BATCH*TSEQ)      // 2048
#define NBLK  128               // persistent recurrence CTAs

// ---------------- device scratch (no allocation allowed) ----------------
__device__ float g_pre [MROWS * G4];     // time-major: [t][b][G4]
__device__ unsigned g_bar_ctr;

// bf16 hi/lo activations (A operand) + weights
__device__ __nv_bfloat16 g_ah [MROWS * HDIM];
__device__ __nv_bfloat16 g_al [MROWS * HDIM];
__device__ __nv_bfloat16 g_w0h[G4 * EDIM];
__device__ __nv_bfloat16 g_w0l[G4 * EDIM];
__device__ __nv_bfloat16 g_w1h[G4 * HDIM];
__device__ __nv_bfloat16 g_w1l[G4 * HDIM];
__device__ __nv_bfloat16 g_fh [VOCAB * HDIM];
__device__ __nv_bfloat16 g_fl [VOCAB * HDIM];

// ======================= helpers =========================================
__device__ __forceinline__ uint32_t smem_u32(const void* p) {
    uint32_t a;
    asm("{ .reg .u64 t; cvta.to.shared.u64 t, %1; cvt.u32.u64 %0, t; }"
        : "=r"(a) : "l"(p));
    return a;
}
#define SWZ(x) ((x) ^ (((x) >> 3) & 0x70))

__device__ __forceinline__ void cpa16(uint32_t dst, const void* src) {
    asm volatile("cp.async.cg.shared.global [%0], [%1], 16;"
                 :: "r"(dst), "l"(src) : "memory");
}
#define CP_COMMIT() asm volatile("cp.async.commit_group;" ::: "memory")
#define CP_WAIT0()  asm volatile("cp.async.wait_group 0;" ::: "memory")
#define CP_WAIT1()  asm volatile("cp.async.wait_group 1;" ::: "memory")
#define CP_WAIT2()  asm volatile("cp.async.wait_group 2;" ::: "memory")

__device__ __forceinline__ void ldsm_x4(uint32_t* r, uint32_t addr) {
    asm volatile("ldmatrix.sync.aligned.m8n8.x4.shared.b16 {%0,%1,%2,%3}, [%4];"
                 : "=r"(r[0]), "=r"(r[1]), "=r"(r[2]), "=r"(r[3]) : "r"(addr));
}
__device__ __forceinline__ void mma_bf16(float* c, const uint32_t* a, const uint32_t* b) {
    asm volatile(
        "mma.sync.aligned.m16n8k16.row.col.f32.bf16.bf16.f32 "
        "{%0,%1,%2,%3}, {%4,%5,%6,%7}, {%8,%9}, {%0,%1,%2,%3};"
        : "+f"(c[0]), "+f"(c[1]), "+f"(c[2]), "+f"(c[3])
        : "r"(a[0]), "r"(a[1]), "r"(a[2]), "r"(a[3]), "r"(b[0]), "r"(b[1]));
}
__device__ __forceinline__ void split_hilo(float x, __nv_bfloat16& h, __nv_bfloat16& l) {
    h = __float2bfloat16(x);
    l = __float2bfloat16(x - __bfloat162float(h));
}

// ============== fp32 -> bf16 hi/lo split conversion (weights) ============
__global__ void cvt_hilo(const float* __restrict__ x,
                         __nv_bfloat16* __restrict__ hi,
                         __nv_bfloat16* __restrict__ lo, int n)
{
    int i = (blockIdx.x * 256 + threadIdx.x) * 4;
    if (i >= n) return;
    float4 v = *(const float4*)(x + i);
    __nv_bfloat16 h0, h1, h2, h3, l0, l1, l2, l3;
    split_hilo(v.x, h0, l0); split_hilo(v.y, h1, l1);
    split_hilo(v.z, h2, l2); split_hilo(v.w, h3, l3);
    __nv_bfloat162 ph0; ph0.x = h0; ph0.y = h1;
    __nv_bfloat162 ph1; ph1.x = h2; ph1.y = h3;
    __nv_bfloat162 pl0; pl0.x = l0; pl0.y = l1;
    __nv_bfloat162 pl1; pl1.x = l2; pl1.y = l3;
    *(__nv_bfloat162*)(hi + i)     = ph0;
    *(__nv_bfloat162*)(hi + i + 2) = ph1;
    *(__nv_bfloat162*)(lo + i)     = pl0;
    *(__nv_bfloat162*)(lo + i + 2) = pl1;
}

// ============== HMMA bf16x3 GEMM: C = A*B^T + bias =======================
// CTA 128M x 256N, 512 threads (16 warps, 4x4), warp tile 32x64, K-chunk 64.
#define A_T   16384                 // 128 rows x 128B
#define B_T   32768                 // 256 rows x 128B
#define STAGE (2*A_T + 2*B_T)       // 96KB
__global__ void __launch_bounds__(512, 1)
gemm_bf16x3(const __nv_bfloat16* __restrict__ Ah, const __nv_bfloat16* __restrict__ Al,
            const __nv_bfloat16* __restrict__ Bh, const __nv_bfloat16* __restrict__ Bl,
            float* __restrict__ C, int M, int N, int K,
            const float* __restrict__ bias1, const float* __restrict__ bias2,
            int permute)
{
    extern __shared__ char dsm[];
    const int tid  = threadIdx.x;
    const int wid  = tid >> 5;
    const int lane = tid & 31;
    const int bm = blockIdx.x * 128;
    const int bn = blockIdx.y * 256;
    const int wm = (wid & 3) * 32;     // 4 warp-rows
    const int wn = (wid >> 2) * 64;    // 4 warp-cols
    const int nk = K >> 6;

    // fold in the grid-barrier reset for the following lstm launch
    if (blockIdx.x == 0 && blockIdx.y == 0 && tid == 0) g_bar_ctr = 0u;

    uint32_t dyn = smem_u32(dsm);
    uint32_t sb0 = (dyn + 1023u) & ~1023u;

    float acc[2][8][4];
    #pragma unroll
    for (int i = 0; i < 2; i++)
        #pragma unroll
        for (int j = 0; j < 8; j++)
            #pragma unroll
            for (int r = 0; r < 4; r++) acc[i][j][r] = 0.f;

    auto issue_load = [&](int kt) {
        const uint32_t st = sb0 + (kt & 1) * STAGE;
        const size_t koff = (size_t)kt * 64;
        #pragma unroll
        for (int i = 0; i < 4; i++) {           // A: hi | lo (2048 chunks)
            int id = i * 512 + tid;
            int tensor = id >> 10;
            int cid = id & 1023;
            int r = cid >> 3, c = cid & 7;
            uint32_t dst = st + tensor * A_T + SWZ((uint32_t)(r * 128 + c * 16));
            const __nv_bfloat16* src = (tensor == 0 ? Ah : Al)
                                     + (size_t)(bm + r) * K + koff + c * 8;
            cpa16(dst, src);
        }
        #pragma unroll
        for (int i = 0; i < 8; i++) {           // B: hi | lo (4096 chunks)
            int id = i * 512 + tid;
            int tensor = id >> 11;
            int cid = id & 2047;
            int r = cid >> 3, c = cid & 7;
            uint32_t dst = st + 2 * A_T + tensor * B_T + SWZ((uint32_t)(r * 128 + c * 16));
            const __nv_bfloat16* src = (tensor == 0 ? Bh : Bl)
                                     + (size_t)(bn + r) * K + koff + c * 8;
            cpa16(dst, src);
        }
        CP_COMMIT();
    };

    issue_load(0);

    const int a_row = wm + (lane & 15);
    const int a_k8  = (lane >> 4) * 8;
    const int b_row = wn + ((lane >> 4) & 1) * 8 + (lane & 7);
    const int b_k8  = ((lane >> 3) & 1) * 8;

    for (int kt = 0; kt < nk; kt++) {
        if (kt + 1 < nk) { issue_load(kt + 1); CP_WAIT1(); }
        else             { CP_WAIT0(); }
        __syncthreads();

        const uint32_t st  = sb0 + (kt & 1) * STAGE;
        const uint32_t sAh = st;
        const uint32_t sAl = st + A_T;
        const uint32_t sBh = st + 2 * A_T;
        const uint32_t sBl = st + 2 * A_T + B_T;

        #pragma unroll
        for (int ks = 0; ks < 4; ks++) {
            const int kb = ks * 16;
            uint32_t aH[2][4], aL[2][4];
            #pragma unroll
            for (int mi = 0; mi < 2; mi++) {
                uint32_t off = SWZ((uint32_t)((a_row + mi * 16) * 128 + (kb + a_k8) * 2));
                ldsm_x4(aH[mi], sAh + off);
                ldsm_x4(aL[mi], sAl + off);
            }
            #pragma unroll
            for (int p = 0; p < 4; p++) {
                uint32_t bH[4], bL[4];
                uint32_t off = SWZ((uint32_t)((b_row + p * 16) * 128 + (kb + b_k8) * 2));
                ldsm_x4(bH, sBh + off);
                ldsm_x4(bL, sBl + off);
                #pragma unroll
                for (int mi = 0; mi < 2; mi++)
                    #pragma unroll
                    for (int j = 0; j < 2; j++) {
                        float* a4 = acc[mi][p * 2 + j];
                        mma_bf16(a4, aH[mi], &bH[j * 2]);
                        mma_bf16(a4, aH[mi], &bL[j * 2]);
                        mma_bf16(a4, aL[mi], &bH[j * 2]);
                    }
            }
        }
        __syncthreads();
    }

    #pragma unroll
    for (int nj = 0; nj < 8; nj++) {
        const int col = bn + wn + nj * 8 + (lane & 3) * 2;
        float b0 = 0.f, b1 = 0.f;
        if (bias1) { b0 += bias1[col]; b1 += bias1[col + 1]; }
        if (bias2) { b0 += bias2[col]; b1 += bias2[col + 1]; }
        #pragma unroll
        for (int mi = 0; mi < 2; mi++) {
            const int r0 = bm + wm + mi * 16 + (lane >> 2);
            const int r1 = r0 + 8;
            int o0 = permute ? ((r0 & 63) * 32 + (r0 >> 6)) : r0;
            int o1 = permute ? ((r1 & 63) * 32 + (r1 >> 6)) : r1;
            float2 v0 = make_float2(acc[mi][nj][0] + b0, acc[mi][nj][1] + b1);
            float2 v1 = make_float2(acc[mi][nj][2] + b0, acc[mi][nj][3] + b1);
            *(float2*)(C + (size_t)o0 * N + col) = v0;
            *(float2*)(C + (size_t)o1 * N + col) = v1;
        }
    }
}

// ---------------- linear(2048->512) + batchnorm -> bf16 hi/lo ------------
__global__ void linbn_kernel(const float* __restrict__ img,
                             const float* __restrict__ W,
                             const float* __restrict__ bias,
                             const float* __restrict__ gamma,
                             const float* __restrict__ beta,
                             __nv_bfloat16* __restrict__ ah,
                             __nv_bfloat16* __restrict__ al)
{
    const int e   = blockIdx.x;
    const int tid = threadIdx.x;
    __shared__ float wrow[IMGF];
    __shared__ float xv[BATCH];

    {
        const float* wsrc = W + (size_t)e * IMGF;
        #pragma unroll
        for (int i = 0; i < 2; i++) {
            int k = (tid + i * 256) * 4;
            *(float4*)&wrow[k] = *(const float4*)(wsrc + k);
        }
    }
    __syncthreads();

    const int lane = tid & 31, wid = tid >> 5;
    float a0 = 0.f, a1 = 0.f, a2 = 0.f, a3 = 0.f;
    for (int k = lane; k < IMGF; k += 32) {
        float wv = wrow[k];
        a0 += img[(size_t)(wid +  0) * IMGF + k] * wv;
        a1 += img[(size_t)(wid +  8) * IMGF + k] * wv;
        a2 += img[(size_t)(wid + 16) * IMGF + k] * wv;
        a3 += img[(size_t)(wid + 24) * IMGF + k] * wv;
    }
    #pragma unroll
    for (int o = 16; o > 0; o >>= 1) {
        a0 += __shfl_xor_sync(0xffffffffu, a0, o);
        a1 += __shfl_xor_sync(0xffffffffu, a1, o);
        a2 += __shfl_xor_sync(0xffffffffu, a2, o);
        a3 += __shfl_xor_sync(0xffffffffu, a3, o);
    }
    if (lane == 0) {
        float bb = bias[e];
        xv[wid +  0] = a0 + bb;
        xv[wid +  8] = a1 + bb;
        xv[wid + 16] = a2 + bb;
        xv[wid + 24] = a3 + bb;
    }
    __syncthreads();

    if (tid < 32) {
        float x = xv[tid];
        float s = x, q = x * x;
        #pragma unroll
        for (int o = 16; o > 0; o >>= 1) {
            s += __shfl_xor_sync(0xffffffffu, s, o);
            q += __shfl_xor_sync(0xffffffffu, q, o);
        }
        float mu  = s * (1.f / 32.f);
        float var = q * (1.f / 32.f) - mu * mu;
        float inv = rsqrtf(var + 1e-5f);
        float y = gamma[e] * (x - mu) * inv + beta[e];
        __nv_bfloat16 h, l;
        split_hilo(y, h, l);
        size_t idx = ((size_t)tid * TSEQ + 0) * EDIM + e;
        ah[idx] = h;
        al[idx] = l;
    }
}

// ---------------- embedding gather -> bf16 hi/lo rows t>=1 ---------------
__global__ void gather_kernel(const int* __restrict__ cap,
                              const float* __restrict__ emb,
                              __nv_bfloat16* __restrict__ ah,
                              __nv_bfloat16* __restrict__ al)
{
    const int t = blockIdx.x + 1;
    const int b = blockIdx.y;
    const int tok = cap[b * TSEQ + (t - 1)];
    const int k = threadIdx.x * 4;
    float4 v = *(const float4*)(emb + (size_t)tok * EDIM + k);
    __nv_bfloat16 h0, h1, h2, h3, l0, l1, l2, l3;
    split_hilo(v.x, h0, l0); split_hilo(v.y, h1, l1);
    split_hilo(v.z, h2, l2); split_hilo(v.w, h3, l3);
    __nv_bfloat162 ph0; ph0.x = h0; ph0.y = h1;
    __nv_bfloat162 ph1; ph1.x = h2; ph1.y = h3;
    __nv_bfloat162 pl0; pl0.x = l0; pl0.y = l1;
    __nv_bfloat162 pl1; pl1.x = l2; pl1.y = l3;
    size_t row = ((size_t)b * TSEQ + t) * EDIM + k;
    *(__nv_bfloat162*)(ah + row)     = ph0;
    *(__nv_bfloat162*)(ah + row + 2) = ph1;
    *(__nv_bfloat162*)(al + row)     = pl0;
    *(__nv_bfloat162*)(al + row + 2) = pl1;
}

// ---------------- persistent HMMA LSTM layer ------------------------------
// 128 CTAs x 256 thr. CTA owns 32 gate-rows (8 units x 4 gates).
// Whh slice bf16 hi/lo in smem; h via ah/al. 4-stage HBUF, 1 sync/chunk.
__global__ void __launch_bounds__(256, 1)
lstm_persist(const float* __restrict__ pre,   // [T][B][G4]
             const float* __restrict__ Whh,   // [G4][HDIM]
             __nv_bfloat16* __restrict__ ah,  // [b*T+t][HDIM]
             __nv_bfloat16* __restrict__ al)
{
    extern __shared__ char sm_raw[];
    uint32_t raw = smem_u32(sm_raw);
    uint32_t sbase = (raw + 127u) & ~127u;
    char* base = sm_raw + (sbase - raw);
    const uint32_t W_HI = 0;
    const uint32_t W_LO = 65536;
    const uint32_t HBUF = 131072;            // 4 stages x 16KB
    float* g_s = (float*)(base + 196608);    // [32][33]

    const int tid  = threadIdx.x;
    const int wid  = tid >> 5;
    const int lane = tid & 31;
    const int u0   = blockIdx.x * 8;

    // one-time: convert Whh slice -> smem bf16 hi/lo (swizzled, 64k tiles)
    #pragma unroll
    for (int i = 0; i < 16; i++) {
        int cell = i * 256 + tid;
        int kt = cell >> 8;
        int r  = (cell >> 3) & 31;
        int cc = cell & 7;
        int jrow = (r >> 3) * HDIM + u0 + (r & 7);
        const float* src = Whh + (size_t)jrow * HDIM + kt * 64 + cc * 8;
        float4 v0 = *(const float4*)src;
        float4 v1 = *(const float4*)(src + 4);
        float f[8] = {v0.x, v0.y, v0.z, v0.w, v1.x, v1.y, v1.z, v1.w};
        uint32_t hi[4], lo[4];
        #pragma unroll
        for (int q = 0; q < 4; q++) {
            __nv_bfloat16 h0, l0, h1, l1;
            split_hilo(f[2*q],   h0, l0);
            split_hilo(f[2*q+1], h1, l1);
            __nv_bfloat162 hp; hp.x = h0; hp.y = h1;
            __nv_bfloat162 lp; lp.x = l0; lp.y = l1;
            hi[q] = *(uint32_t*)&hp;
            lo[q] = *(uint32_t*)&lp;
        }
        uint32_t off = kt * 4096 + SWZ((uint32_t)(r * 128 + cc * 16));
        *(uint4*)(base + W_HI + off) = make_uint4(hi[0], hi[1], hi[2], hi[3]);
        *(uint4*)(base + W_LO + off) = make_uint4(lo[0], lo[1], lo[2], lo[3]);
    }
    __syncthreads();

    const int wm = (wid & 1) * 16;
    const int wn = (wid >> 1) * 8;
    const int a_row = wm + (lane & 15);
    const int a_k8  = (lane >> 4) * 8;
    const int b_row = wn + (lane & 7);
    const int b_ku  = (lane >> 3) & 3;

    const int hr = tid >> 3;
    const int hc = tid & 7;
    const uint32_t hswz = SWZ((uint32_t)(hr * 128 + hc * 16));

    const int pb = tid >> 3;
    const int pu = tid & 7;

    // epilogue coords (precomputed)
    const int jloc = wn + (lane & 3) * 2;
    const int jrow_e = (jloc >> 3) * HDIM + u0 + (jloc & 7);
    const int br = wm + (lane >> 2);

    float c_reg = 0.f;
    unsigned gen = 0;

    for (int t = 0; t < TSEQ; t++) {
        float acc[4] = {0.f, 0.f, 0.f, 0.f};

        // prefetch pre[t] early (independent of h)
        const float* pt = pre + (size_t)t * BATCH * G4;
        float2 p0 = *(const float2*)(pt + (size_t)br * G4 + jrow_e);
        float2 p1 = *(const float2*)(pt + (size_t)(br + 8) * G4 + jrow_e);

        if (t > 0) {
            const size_t hrow_base = ((size_t)hr * TSEQ + (t - 1)) * HDIM + hc * 8;
            auto issue_chunk = [&](int c) {
                const uint32_t d = sbase + HBUF + (c & 3) * 16384 + hswz;
                const size_t g = hrow_base + (size_t)c * 128;
                cpa16(d,         ah + g);
                cpa16(d + 4096,  ah + g + 64);
                cpa16(d + 8192,  al + g);
                cpa16(d + 12288, al + g + 64);
                CP_COMMIT();
            };
            issue_chunk(0);
            issue_chunk(1);
            issue_chunk(2);
            for (int c = 0; c < 8; c++) {
                if (c < 6) { CP_WAIT2(); }
                else if (c == 6) { CP_WAIT1(); }
                else { CP_WAIT0(); }
                __syncthreads();
                const uint32_t stg = sbase + HBUF + (c & 3) * 16384;
                #pragma unroll
                for (int sub = 0; sub < 2; sub++) {
                    const uint32_t wc = (uint32_t)(2 * c + sub) * 4096;
                    const uint32_t hb_hi = stg + sub * 4096;
                    const uint32_t hb_lo = stg + 8192 + sub * 4096;
                    #pragma unroll
                    for (int kk2 = 0; kk2 < 2; kk2++) {
                        uint32_t bH4[4], bL4[4];
                        uint32_t boff = wc + SWZ((uint32_t)(b_row * 128 + kk2 * 64 + b_ku * 16));
                        ldsm_x4(bH4, sbase + W_HI + boff);
                        ldsm_x4(bL4, sbase + W_LO + boff);
                        #pragma unroll
                        for (int kh = 0; kh < 2; kh++) {
                            const int ks = kk2 * 2 + kh;
                            uint32_t aH4[4], aL4[4];
                            uint32_t aoff = SWZ((uint32_t)(a_row * 128 + ks * 32 + a_k8 * 2));
                            ldsm_x4(aH4, hb_hi + aoff);
                            ldsm_x4(aL4, hb_lo + aoff);
                            mma_bf16(acc, aH4, &bH4[kh * 2]);
                            mma_bf16(acc, aH4, &bL4[kh * 2]);
                            mma_bf16(acc, aL4, &bH4[kh * 2]);
                        }
                    }
                }
                if (c + 3 < 8) issue_chunk(c + 3);
            }
            __syncthreads();   // all warps done with last stage before g_s reuse
        }

        // epilogue: g = acc + pre[t] (prefetched)
        g_s[jloc * 33 + br]           = acc[0] + p0.x;
        g_s[(jloc + 1) * 33 + br]     = acc[1] + p0.y;
        g_s[jloc * 33 + br + 8]       = acc[2] + p1.x;
        g_s[(jloc + 1) * 33 + br + 8] = acc[3] + p1.y;
        __syncthreads();

        // pointwise
        {
            float gi = g_s[pu * 33 + pb];
            float gf = g_s[(8 + pu) * 33 + pb];
            float gg = g_s[(16 + pu) * 33 + pb];
            float go = g_s[(24 + pu) * 33 + pb];
            float si = 1.f / (1.f + expf(-gi));
            float sf = 1.f / (1.f + expf(-gf));
            float so = 1.f / (1.f + expf(-go));
            c_reg = sf * c_reg + si * tanhf(gg);
            float hn = so * tanhf(c_reg);
            __nv_bfloat16 hh, hl;
            split_hilo(hn, hh, hl);
            size_t orow = ((size_t)pb * TSEQ + t) * HDIM + u0 + pu;
            ah[orow] = hh;
            al[orow] = hl;
        }
        __syncthreads();

        if (t + 1 < TSEQ) {
            gen++;
            if (tid == 0) {
                asm volatile("red.release.gpu.global.add.u32 [%0], 1;"
                             :: "l"(&g_bar_ctr) : "memory");
                unsigned tgt = gen * NBLK, v;
                do {
                    asm volatile("ld.acquire.gpu.global.u32 %0, [%1];"
                                 : "=r"(v) : "l"(&g_bar_ctr) : "memory");
                } while (v < tgt);
            }
            __syncthreads();
        }
    }
}

// ---------------- host launch --------------------------------------------
extern "C" void kernel_launch(void* const* d_in, const int* in_sizes, int n_in,
                              void* d_out, int out_size)
{
    const float* image = (const float*)d_in[0];
    const int*   caps  = (const int*)  d_in[1];
    const float* lin_W = (const float*)d_in[2];
    const float* lin_b = (const float*)d_in[3];
    const float* bn_g  = (const float*)d_in[4];
    const float* bn_b  = (const float*)d_in[5];
    const float* emb   = (const float*)d_in[6];
    const float* Wih0  = (const float*)d_in[7];
    const float* Whh0  = (const float*)d_in[8];
    const float* bih0  = (const float*)d_in[9];
    const float* bhh0  = (const float*)d_in[10];
    const float* Wih1  = (const float*)d_in[11];
    const float* Whh1  = (const float*)d_in[12];
    const float* bih1  = (const float*)d_in[13];
    const float* bhh1  = (const float*)d_in[14];
    const float* fc_W  = (const float*)d_in[15];
    const float* fc_b  = (const float*)d_in[16];
    float* out = (float*)d_out;

    float *pre;
    __nv_bfloat16 *ah, *al, *w0h, *w0l, *w1h, *w1l, *fh, *fl;
    cudaGetSymbolAddress((void**)&pre, g_pre);
    cudaGetSymbolAddress((void**)&ah,  g_ah);
    cudaGetSymbolAddress((void**)&al,  g_al);
    cudaGetSymbolAddress((void**)&w0h, g_w0h);
    cudaGetSymbolAddress((void**)&w0l, g_w0l);
    cudaGetSymbolAddress((void**)&w1h, g_w1h);
    cudaGetSymbolAddress((void**)&w1l, g_w1l);
    cudaGetSymbolAddress((void**)&fh,  g_fh);
    cudaGetSymbolAddress((void**)&fl,  g_fl);

    static int smem_set = 0;
    const int GEMM_SMEM = 2 * STAGE + 1024;                  // ~193KB
    const int LSTM_SMEM = 196608 + 32 * 33 * 4 + 256;        // ~201KB
    if (!smem_set) {
        cudaFuncSetAttribute(gemm_bf16x3,
                             cudaFuncAttributeMaxDynamicSharedMemorySize, GEMM_SMEM);
        cudaFuncSetAttribute(lstm_persist,
                             cudaFuncAttributeMaxDynamicSharedMemorySize, LSTM_SMEM);
        smem_set = 1;
    }

    // inputs -> ah/al rows (K=EDIM layout)
    linbn_kernel<<<EDIM, 256>>>(image, lin_W, lin_b, bn_g, bn_b, ah, al);
    gather_kernel<<<dim3(TSEQ - 1, BATCH), 128>>>(caps, emb, ah, al);

    // layer-0 input weights, then pre0 GEMM (4th launch -> ncu window)
    cvt_hilo<<<(G4 * EDIM / 4 + 255) / 256, 256>>>(Wih0, w0h, w0l, G4 * EDIM);
    gemm_bf16x3<<<dim3(MROWS / 128, G4 / 256), 512, GEMM_SMEM>>>(
        ah, al, w0h, w0l, pre, MROWS, G4, EDIM, bih0, bhh0, 1);

    // remaining weight conversions
    cvt_hilo<<<(G4 * HDIM / 4 + 255) / 256, 256>>>(Wih1, w1h, w1l, G4 * HDIM);
    cvt_hilo<<<(VOCAB * HDIM / 4 + 255) / 256, 256>>>(fc_W, fh, fl, VOCAB * HDIM);

    // layer-0 recurrence (bar reset folded into gemm above)
    lstm_persist<<<NBLK, 256, LSTM_SMEM>>>(pre, Whh0, ah, al);

    // pre1 = hs0 @ Wih1^T + biases (resets bar for lstm1)
    gemm_bf16x3<<<dim3(MROWS / 128, G4 / 256), 512, GEMM_SMEM>>>(
        ah, al, w1h, w1l, pre, MROWS, G4, HDIM, bih1, bhh1, 1);

    // layer-1 recurrence
    lstm_persist<<<NBLK, 256, LSTM_SMEM>>>(pre, Whh1, ah, al);

    // logits = hs1 @ fc_W^T + fc_b
    gemm_bf16x3<<<dim3(MROWS / 128, VOCAB / 256), 512, GEMM_SMEM>>>(
        ah, al, fh, fl, out, MROWS, VOCAB, HDIM, fc_b, nullptr, 0);
}

// round 8
// speedup vs baseline: 3.8642x; 1.0018x over previous
#include <cuda_runtime.h>
#include <cuda_bf16.h>
#include <math.h>
#include <stdint.h>

// Problem dims
#define VOCAB 32000
#define HDIM  1024
#define EDIM  512
#define BATCH 32
#define TSEQ  64
#define IMGF  2048
#define G4    (4*HDIM)          // 4096
#define MROWS (BATCH*TSEQ)      // 2048
#define NBLK  128               // persistent recurrence CTAs

// ---------------- device scratch (no allocation allowed) ----------------
__device__ float g_pre [MROWS * G4];     // time-major: [t][b][G4]
__device__ unsigned g_bar_ctr;

// bf16 hi/lo activations (A operand) + weights
__device__ __nv_bfloat16 g_ah [MROWS * HDIM];
__device__ __nv_bfloat16 g_al [MROWS * HDIM];
__device__ __nv_bfloat16 g_w0h[G4 * EDIM];
__device__ __nv_bfloat16 g_w0l[G4 * EDIM];
__device__ __nv_bfloat16 g_w1h[G4 * HDIM];
__device__ __nv_bfloat16 g_w1l[G4 * HDIM];
__device__ __nv_bfloat16 g_fh [VOCAB * HDIM];
__device__ __nv_bfloat16 g_fl [VOCAB * HDIM];

// ======================= helpers =========================================
__device__ __forceinline__ uint32_t smem_u32(const void* p) {
    uint32_t a;
    asm("{ .reg .u64 t; cvta.to.shared.u64 t, %1; cvt.u32.u64 %0, t; }"
        : "=r"(a) : "l"(p));
    return a;
}
#define SWZ(x) ((x) ^ (((x) >> 3) & 0x70))

__device__ __forceinline__ void cpa16(uint32_t dst, const void* src) {
    asm volatile("cp.async.cg.shared.global [%0], [%1], 16;"
                 :: "r"(dst), "l"(src) : "memory");
}
#define CP_COMMIT() asm volatile("cp.async.commit_group;" ::: "memory")
#define CP_WAIT0()  asm volatile("cp.async.wait_group 0;" ::: "memory")
#define CP_WAIT1()  asm volatile("cp.async.wait_group 1;" ::: "memory")
#define CP_WAIT2()  asm volatile("cp.async.wait_group 2;" ::: "memory")

__device__ __forceinline__ void ldsm_x4(uint32_t* r, uint32_t addr) {
    asm volatile("ldmatrix.sync.aligned.m8n8.x4.shared.b16 {%0,%1,%2,%3}, [%4];"
                 : "=r"(r[0]), "=r"(r[1]), "=r"(r[2]), "=r"(r[3]) : "r"(addr));
}
__device__ __forceinline__ void mma_bf16(float* c, const uint32_t* a, const uint32_t* b) {
    asm volatile(
        "mma.sync.aligned.m16n8k16.row.col.f32.bf16.bf16.f32 "
        "{%0,%1,%2,%3}, {%4,%5,%6,%7}, {%8,%9}, {%0,%1,%2,%3};"
        : "+f"(c[0]), "+f"(c[1]), "+f"(c[2]), "+f"(c[3])
        : "r"(a[0]), "r"(a[1]), "r"(a[2]), "r"(a[3]), "r"(b[0]), "r"(b[1]));
}
__device__ __forceinline__ void split_hilo(float x, __nv_bfloat16& h, __nv_bfloat16& l) {
    h = __float2bfloat16(x);
    l = __float2bfloat16(x - __bfloat162float(h));
}

// ============== fp32 -> bf16 hi/lo split conversion (weights) ============
__global__ void cvt_hilo(const float* __restrict__ x,
                         __nv_bfloat16* __restrict__ hi,
                         __nv_bfloat16* __restrict__ lo, int n)
{
    int i = (blockIdx.x * 256 + threadIdx.x) * 4;
    if (i >= n) return;
    float4 v = *(const float4*)(x + i);
    __nv_bfloat16 h0, h1, h2, h3, l0, l1, l2, l3;
    split_hilo(v.x, h0, l0); split_hilo(v.y, h1, l1);
    split_hilo(v.z, h2, l2); split_hilo(v.w, h3, l3);
    __nv_bfloat162 ph0; ph0.x = h0; ph0.y = h1;
    __nv_bfloat162 ph1; ph1.x = h2; ph1.y = h3;
    __nv_bfloat162 pl0; pl0.x = l0; pl0.y = l1;
    __nv_bfloat162 pl1; pl1.x = l2; pl1.y = l3;
    *(__nv_bfloat162*)(hi + i)     = ph0;
    *(__nv_bfloat162*)(hi + i + 2) = ph1;
    *(__nv_bfloat162*)(lo + i)     = pl0;
    *(__nv_bfloat162*)(lo + i + 2) = pl1;
}

// ============== HMMA bf16x3 GEMM: C = A*B^T + bias =======================
// CTA 128M x 128N, 256 threads (8 warps 4x2), warp tile 32x64, K-chunk 64.
// 3-stage smem pipeline, 1 sync/chunk, fragment double-buffering.
#define TEN_T 16384                 // one tensor tile: 128 rows x 128B
#define STAGE (4*TEN_T)             // Ah|Al|Bh|Bl = 64KB
__global__ void __launch_bounds__(256, 1)
gemm_bf16x3(const __nv_bfloat16* __restrict__ Ah, const __nv_bfloat16* __restrict__ Al,
            const __nv_bfloat16* __restrict__ Bh, const __nv_bfloat16* __restrict__ Bl,
            float* __restrict__ C, int M, int N, int K,
            const float* __restrict__ bias1, const float* __restrict__ bias2,
            int permute)
{
    extern __shared__ char dsm[];
    const int tid  = threadIdx.x;
    const int wid  = tid >> 5;
    const int lane = tid & 31;
    const int bm = blockIdx.x * 128;
    const int bn = blockIdx.y * 128;
    const int wm = (wid & 3) * 32;     // 4 warp-rows
    const int wn = (wid >> 2) * 64;    // 2 warp-cols
    const int nk = K >> 6;

    // fold in the grid-barrier reset for the following lstm launch
    if (blockIdx.x == 0 && blockIdx.y == 0 && tid == 0) g_bar_ctr = 0u;

    uint32_t dyn = smem_u32(dsm);
    uint32_t sb0 = (dyn + 1023u) & ~1023u;

    float acc[2][8][4];
    #pragma unroll
    for (int i = 0; i < 2; i++)
        #pragma unroll
        for (int j = 0; j < 8; j++)
            #pragma unroll
            for (int r = 0; r < 4; r++) acc[i][j][r] = 0.f;

    auto issue_load = [&](int kt, int stg) {
        const uint32_t st = sb0 + (uint32_t)stg * STAGE;
        const size_t koff = (size_t)kt * 64;
        #pragma unroll
        for (int i = 0; i < 16; i++) {
            int id = i * 256 + tid;
            int tensor = id >> 10;              // 0..3: Ah Al Bh Bl
            int cid = id & 1023;
            int r = cid >> 3, c = cid & 7;
            uint32_t dst = st + tensor * TEN_T + SWZ((uint32_t)(r * 128 + c * 16));
            const __nv_bfloat16* src;
            if (tensor == 0)      src = Ah + (size_t)(bm + r) * K + koff + c * 8;
            else if (tensor == 1) src = Al + (size_t)(bm + r) * K + koff + c * 8;
            else if (tensor == 2) src = Bh + (size_t)(bn + r) * K + koff + c * 8;
            else                  src = Bl + (size_t)(bn + r) * K + koff + c * 8;
            cpa16(dst, src);
        }
        CP_COMMIT();
    };

    issue_load(0, 0);
    if (nk > 1) issue_load(1, 1);

    const int a_row = wm + (lane & 15);
    const int a_k8  = (lane >> 4) * 8;
    const int b_row = wn + ((lane >> 4) & 1) * 8 + (lane & 7);
    const int b_k8  = ((lane >> 3) & 1) * 8;

    // fragment double buffers
    uint32_t aH[2][2][4], aL[2][2][4], bH[2][4][4], bL[2][4][4];

    int s_cur = 0, s_nxt = 2;
    for (int kt = 0; kt < nk; kt++) {
        if (kt + 1 < nk) { CP_WAIT1(); } else { CP_WAIT0(); }
        __syncthreads();
        if (kt + 2 < nk) issue_load(kt + 2, s_nxt);

        const uint32_t st  = sb0 + (uint32_t)s_cur * STAGE;
        const uint32_t sAh = st;
        const uint32_t sAl = st + TEN_T;
        const uint32_t sBh = st + 2 * TEN_T;
        const uint32_t sBl = st + 3 * TEN_T;

        auto load_frags = [&](int buf, int ksv) {
            const int kb = ksv * 16;
            #pragma unroll
            for (int mi = 0; mi < 2; mi++) {
                uint32_t off = SWZ((uint32_t)((a_row + mi * 16) * 128 + (kb + a_k8) * 2));
                ldsm_x4(aH[buf][mi], sAh + off);
                ldsm_x4(aL[buf][mi], sAl + off);
            }
            #pragma unroll
            for (int p = 0; p < 4; p++) {
                uint32_t off = SWZ((uint32_t)((b_row + p * 16) * 128 + (kb + b_k8) * 2));
                ldsm_x4(bH[buf][p], sBh + off);
                ldsm_x4(bL[buf][p], sBl + off);
            }
        };

        load_frags(0, 0);
        #pragma unroll
        for (int ks = 0; ks < 4; ks++) {
            const int cb = ks & 1;
            if (ks < 3) load_frags(cb ^ 1, ks + 1);
            // term-major: 16 independent MMAs per term
            #pragma unroll
            for (int mi = 0; mi < 2; mi++)
                #pragma unroll
                for (int p = 0; p < 4; p++)
                    #pragma unroll
                    for (int j = 0; j < 2; j++)
                        mma_bf16(acc[mi][p * 2 + j], aH[cb][mi], &bH[cb][p][j * 2]);
            #pragma unroll
            for (int mi = 0; mi < 2; mi++)
                #pragma unroll
                for (int p = 0; p < 4; p++)
                    #pragma unroll
                    for (int j = 0; j < 2; j++)
                        mma_bf16(acc[mi][p * 2 + j], aH[cb][mi], &bL[cb][p][j * 2]);
            #pragma unroll
            for (int mi = 0; mi < 2; mi++)
                #pragma unroll
                for (int p = 0; p < 4; p++)
                    #pragma unroll
                    for (int j = 0; j < 2; j++)
                        mma_bf16(acc[mi][p * 2 + j], aL[cb][mi], &bH[cb][p][j * 2]);
        }

        s_cur = (s_cur == 2) ? 0 : s_cur + 1;
        s_nxt = (s_nxt == 2) ? 0 : s_nxt + 1;
    }

    #pragma unroll
    for (int nj = 0; nj < 8; nj++) {
        const int col = bn + wn + nj * 8 + (lane & 3) * 2;
        float b0 = 0.f, b1 = 0.f;
        if (bias1) { b0 += bias1[col]; b1 += bias1[col + 1]; }
        if (bias2) { b0 += bias2[col]; b1 += bias2[col + 1]; }
        #pragma unroll
        for (int mi = 0; mi < 2; mi++) {
            const int r0 = bm + wm + mi * 16 + (lane >> 2);
            const int r1 = r0 + 8;
            int o0 = permute ? ((r0 & 63) * 32 + (r0 >> 6)) : r0;
            int o1 = permute ? ((r1 & 63) * 32 + (r1 >> 6)) : r1;
            float2 v0 = make_float2(acc[mi][nj][0] + b0, acc[mi][nj][1] + b1);
            float2 v1 = make_float2(acc[mi][nj][2] + b0, acc[mi][nj][3] + b1);
            *(float2*)(C + (size_t)o0 * N + col) = v0;
            *(float2*)(C + (size_t)o1 * N + col) = v1;
        }
    }
}

// ---------------- linear(2048->512) + batchnorm -> bf16 hi/lo ------------
__global__ void linbn_kernel(const float* __restrict__ img,
                             const float* __restrict__ W,
                             const float* __restrict__ bias,
                             const float* __restrict__ gamma,
                             const float* __restrict__ beta,
                             __nv_bfloat16* __restrict__ ah,
                             __nv_bfloat16* __restrict__ al)
{
    const int e   = blockIdx.x;
    const int tid = threadIdx.x;
    __shared__ float wrow[IMGF];
    __shared__ float xv[BATCH];

    {
        const float* wsrc = W + (size_t)e * IMGF;
        #pragma unroll
        for (int i = 0; i < 2; i++) {
            int k = (tid + i * 256) * 4;
            *(float4*)&wrow[k] = *(const float4*)(wsrc + k);
        }
    }
    __syncthreads();

    const int lane = tid & 31, wid = tid >> 5;
    float a0 = 0.f, a1 = 0.f, a2 = 0.f, a3 = 0.f;
    for (int k = lane; k < IMGF; k += 32) {
        float wv = wrow[k];
        a0 += img[(size_t)(wid +  0) * IMGF + k] * wv;
        a1 += img[(size_t)(wid +  8) * IMGF + k] * wv;
        a2 += img[(size_t)(wid + 16) * IMGF + k] * wv;
        a3 += img[(size_t)(wid + 24) * IMGF + k] * wv;
    }
    #pragma unroll
    for (int o = 16; o > 0; o >>= 1) {
        a0 += __shfl_xor_sync(0xffffffffu, a0, o);
        a1 += __shfl_xor_sync(0xffffffffu, a1, o);
        a2 += __shfl_xor_sync(0xffffffffu, a2, o);
        a3 += __shfl_xor_sync(0xffffffffu, a3, o);
    }
    if (lane == 0) {
        float bb = bias[e];
        xv[wid +  0] = a0 + bb;
        xv[wid +  8] = a1 + bb;
        xv[wid + 16] = a2 + bb;
        xv[wid + 24] = a3 + bb;
    }
    __syncthreads();

    if (tid < 32) {
        float x = xv[tid];
        float s = x, q = x * x;
        #pragma unroll
        for (int o = 16; o > 0; o >>= 1) {
            s += __shfl_xor_sync(0xffffffffu, s, o);
            q += __shfl_xor_sync(0xffffffffu, q, o);
        }
        float mu  = s * (1.f / 32.f);
        float var = q * (1.f / 32.f) - mu * mu;
        float inv = rsqrtf(var + 1e-5f);
        float y = gamma[e] * (x - mu) * inv + beta[e];
        __nv_bfloat16 h, l;
        split_hilo(y, h, l);
        size_t idx = ((size_t)tid * TSEQ + 0) * EDIM + e;
        ah[idx] = h;
        al[idx] = l;
    }
}

// ---------------- embedding gather -> bf16 hi/lo rows t>=1 ---------------
__global__ void gather_kernel(const int* __restrict__ cap,
                              const float* __restrict__ emb,
                              __nv_bfloat16* __restrict__ ah,
                              __nv_bfloat16* __restrict__ al)
{
    const int t = blockIdx.x + 1;
    const int b = blockIdx.y;
    const int tok = cap[b * TSEQ + (t - 1)];
    const int k = threadIdx.x * 4;
    float4 v = *(const float4*)(emb + (size_t)tok * EDIM + k);
    __nv_bfloat16 h0, h1, h2, h3, l0, l1, l2, l3;
    split_hilo(v.x, h0, l0); split_hilo(v.y, h1, l1);
    split_hilo(v.z, h2, l2); split_hilo(v.w, h3, l3);
    __nv_bfloat162 ph0; ph0.x = h0; ph0.y = h1;
    __nv_bfloat162 ph1; ph1.x = h2; ph1.y = h3;
    __nv_bfloat162 pl0; pl0.x = l0; pl0.y = l1;
    __nv_bfloat162 pl1; pl1.x = l2; pl1.y = l3;
    size_t row = ((size_t)b * TSEQ + t) * EDIM + k;
    *(__nv_bfloat162*)(ah + row)     = ph0;
    *(__nv_bfloat162*)(ah + row + 2) = ph1;
    *(__nv_bfloat162*)(al + row)     = pl0;
    *(__nv_bfloat162*)(al + row + 2) = pl1;
}

// ---------------- persistent HMMA LSTM layer ------------------------------
// 128 CTAs x 256 thr. CTA owns 32 gate-rows (8 units x 4 gates).
// Whh slice bf16 hi/lo in smem; h via ah/al. 4-stage HBUF, 1 sync/chunk.
__global__ void __launch_bounds__(256, 1)
lstm_persist(const float* __restrict__ pre,   // [T][B][G4]
             const float* __restrict__ Whh,   // [G4][HDIM]
             __nv_bfloat16* __restrict__ ah,  // [b*T+t][HDIM]
             __nv_bfloat16* __restrict__ al)
{
    extern __shared__ char sm_raw[];
    uint32_t raw = smem_u32(sm_raw);
    uint32_t sbase = (raw + 127u) & ~127u;
    char* base = sm_raw + (sbase - raw);
    const uint32_t W_HI = 0;
    const uint32_t W_LO = 65536;
    const uint32_t HBUF = 131072;            // 4 stages x 16KB
    float* g_s = (float*)(base + 196608);    // [32][33]

    const int tid  = threadIdx.x;
    const int wid  = tid >> 5;
    const int lane = tid & 31;
    const int u0   = blockIdx.x * 8;

    // one-time: convert Whh slice -> smem bf16 hi/lo (swizzled, 64k tiles)
    #pragma unroll
    for (int i = 0; i < 16; i++) {
        int cell = i * 256 + tid;
        int kt = cell >> 8;
        int r  = (cell >> 3) & 31;
        int cc = cell & 7;
        int jrow = (r >> 3) * HDIM + u0 + (r & 7);
        const float* src = Whh + (size_t)jrow * HDIM + kt * 64 + cc * 8;
        float4 v0 = *(const float4*)src;
        float4 v1 = *(const float4*)(src + 4);
        float f[8] = {v0.x, v0.y, v0.z, v0.w, v1.x, v1.y, v1.z, v1.w};
        uint32_t hi[4], lo[4];
        #pragma unroll
        for (int q = 0; q < 4; q++) {
            __nv_bfloat16 h0, l0, h1, l1;
            split_hilo(f[2*q],   h0, l0);
            split_hilo(f[2*q+1], h1, l1);
            __nv_bfloat162 hp; hp.x = h0; hp.y = h1;
            __nv_bfloat162 lp; lp.x = l0; lp.y = l1;
            hi[q] = *(uint32_t*)&hp;
            lo[q] = *(uint32_t*)&lp;
        }
        uint32_t off = kt * 4096 + SWZ((uint32_t)(r * 128 + cc * 16));
        *(uint4*)(base + W_HI + off) = make_uint4(hi[0], hi[1], hi[2], hi[3]);
        *(uint4*)(base + W_LO + off) = make_uint4(lo[0], lo[1], lo[2], lo[3]);
    }
    __syncthreads();

    const int wm = (wid & 1) * 16;
    const int wn = (wid >> 1) * 8;
    const int a_row = wm + (lane & 15);
    const int a_k8  = (lane >> 4) * 8;
    const int b_row = wn + (lane & 7);
    const int b_ku  = (lane >> 3) & 3;

    const int hr = tid >> 3;
    const int hc = tid & 7;
    const uint32_t hswz = SWZ((uint32_t)(hr * 128 + hc * 16));

    const int pb = tid >> 3;
    const int pu = tid & 7;

    // epilogue coords (precomputed)
    const int jloc = wn + (lane & 3) * 2;
    const int jrow_e = (jloc >> 3) * HDIM + u0 + (jloc & 7);
    const int br = wm + (lane >> 2);

    float c_reg = 0.f;
    unsigned gen = 0;

    for (int t = 0; t < TSEQ; t++) {
        float acc[4] = {0.f, 0.f, 0.f, 0.f};

        // prefetch pre[t] early (independent of h)
        const float* pt = pre + (size_t)t * BATCH * G4;
        float2 p0 = *(const float2*)(pt + (size_t)br * G4 + jrow_e);
        float2 p1 = *(const float2*)(pt + (size_t)(br + 8) * G4 + jrow_e);

        if (t > 0) {
            const size_t hrow_base = ((size_t)hr * TSEQ + (t - 1)) * HDIM + hc * 8;
            auto issue_chunk = [&](int c) {
                const uint32_t d = sbase + HBUF + (c & 3) * 16384 + hswz;
                const size_t g = hrow_base + (size_t)c * 128;
                cpa16(d,         ah + g);
                cpa16(d + 4096,  ah + g + 64);
                cpa16(d + 8192,  al + g);
                cpa16(d + 12288, al + g + 64);
                CP_COMMIT();
            };
            issue_chunk(0);
            issue_chunk(1);
            issue_chunk(2);
            for (int c = 0; c < 8; c++) {
                if (c < 6) { CP_WAIT2(); }
                else if (c == 6) { CP_WAIT1(); }
                else { CP_WAIT0(); }
                __syncthreads();
                const uint32_t stg = sbase + HBUF + (c & 3) * 16384;
                #pragma unroll
                for (int sub = 0; sub < 2; sub++) {
                    const uint32_t wc = (uint32_t)(2 * c + sub) * 4096;
                    const uint32_t hb_hi = stg + sub * 4096;
                    const uint32_t hb_lo = stg + 8192 + sub * 4096;
                    #pragma unroll
                    for (int kk2 = 0; kk2 < 2; kk2++) {
                        uint32_t bH4[4], bL4[4];
                        uint32_t boff = wc + SWZ((uint32_t)(b_row * 128 + kk2 * 64 + b_ku * 16));
                        ldsm_x4(bH4, sbase + W_HI + boff);
                        ldsm_x4(bL4, sbase + W_LO + boff);
                        #pragma unroll
                        for (int kh = 0; kh < 2; kh++) {
                            const int ks = kk2 * 2 + kh;
                            uint32_t aH4[4], aL4[4];
                            uint32_t aoff = SWZ((uint32_t)(a_row * 128 + ks * 32 + a_k8 * 2));
                            ldsm_x4(aH4, hb_hi + aoff);
                            ldsm_x4(aL4, hb_lo + aoff);
                            mma_bf16(acc, aH4, &bH4[kh * 2]);
                            mma_bf16(acc, aH4, &bL4[kh * 2]);
                            mma_bf16(acc, aL4, &bH4[kh * 2]);
                        }
                    }
                }
                if (c + 3 < 8) issue_chunk(c + 3);
            }
            __syncthreads();   // all warps done with last stage before g_s reuse
        }

        // epilogue: g = acc + pre[t] (prefetched)
        g_s[jloc * 33 + br]           = acc[0] + p0.x;
        g_s[(jloc + 1) * 33 + br]     = acc[1] + p0.y;
        g_s[jloc * 33 + br + 8]       = acc[2] + p1.x;
        g_s[(jloc + 1) * 33 + br + 8] = acc[3] + p1.y;
        __syncthreads();

        // pointwise
        {
            float gi = g_s[pu * 33 + pb];
            float gf = g_s[(8 + pu) * 33 + pb];
            float gg = g_s[(16 + pu) * 33 + pb];
            float go = g_s[(24 + pu) * 33 + pb];
            float si = 1.f / (1.f + expf(-gi));
            float sf = 1.f / (1.f + expf(-gf));
            float so = 1.f / (1.f + expf(-go));
            c_reg = sf * c_reg + si * tanhf(gg);
            float hn = so * tanhf(c_reg);
            __nv_bfloat16 hh, hl;
            split_hilo(hn, hh, hl);
            size_t orow = ((size_t)pb * TSEQ + t) * HDIM + u0 + pu;
            ah[orow] = hh;
            al[orow] = hl;
        }
        __syncthreads();

        if (t + 1 < TSEQ) {
            gen++;
            if (tid == 0) {
                asm volatile("red.release.gpu.global.add.u32 [%0], 1;"
                             :: "l"(&g_bar_ctr) : "memory");
                unsigned tgt = gen * NBLK, v;
                do {
                    asm volatile("ld.acquire.gpu.global.u32 %0, [%1];"
                                 : "=r"(v) : "l"(&g_bar_ctr) : "memory");
                } while (v < tgt);
            }
            __syncthreads();
        }
    }
}

// ---------------- host launch --------------------------------------------
extern "C" void kernel_launch(void* const* d_in, const int* in_sizes, int n_in,
                              void* d_out, int out_size)
{
    const float* image = (const float*)d_in[0];
    const int*   caps  = (const int*)  d_in[1];
    const float* lin_W = (const float*)d_in[2];
    const float* lin_b = (const float*)d_in[3];
    const float* bn_g  = (const float*)d_in[4];
    const float* bn_b  = (const float*)d_in[5];
    const float* emb   = (const float*)d_in[6];
    const float* Wih0  = (const float*)d_in[7];
    const float* Whh0  = (const float*)d_in[8];
    const float* bih0  = (const float*)d_in[9];
    const float* bhh0  = (const float*)d_in[10];
    const float* Wih1  = (const float*)d_in[11];
    const float* Whh1  = (const float*)d_in[12];
    const float* bih1  = (const float*)d_in[13];
    const float* bhh1  = (const float*)d_in[14];
    const float* fc_W  = (const float*)d_in[15];
    const float* fc_b  = (const float*)d_in[16];
    float* out = (float*)d_out;

    float *pre;
    __nv_bfloat16 *ah, *al, *w0h, *w0l, *w1h, *w1l, *fh, *fl;
    cudaGetSymbolAddress((void**)&pre, g_pre);
    cudaGetSymbolAddress((void**)&ah,  g_ah);
    cudaGetSymbolAddress((void**)&al,  g_al);
    cudaGetSymbolAddress((void**)&w0h, g_w0h);
    cudaGetSymbolAddress((void**)&w0l, g_w0l);
    cudaGetSymbolAddress((void**)&w1h, g_w1h);
    cudaGetSymbolAddress((void**)&w1l, g_w1l);
    cudaGetSymbolAddress((void**)&fh,  g_fh);
    cudaGetSymbolAddress((void**)&fl,  g_fl);

    static int smem_set = 0;
    const int GEMM_SMEM = 3 * STAGE + 1024;                  // ~193KB
    const int LSTM_SMEM = 196608 + 32 * 33 * 4 + 256;        // ~201KB
    if (!smem_set) {
        cudaFuncSetAttribute(gemm_bf16x3,
                             cudaFuncAttributeMaxDynamicSharedMemorySize, GEMM_SMEM);
        cudaFuncSetAttribute(lstm_persist,
                             cudaFuncAttributeMaxDynamicSharedMemorySize, LSTM_SMEM);
        smem_set = 1;
    }

    // inputs -> ah/al rows (K=EDIM layout)
    linbn_kernel<<<EDIM, 256>>>(image, lin_W, lin_b, bn_g, bn_b, ah, al);
    gather_kernel<<<dim3(TSEQ - 1, BATCH), 128>>>(caps, emb, ah, al);

    // layer-0 input weights, then pre0 GEMM (4th launch -> ncu window)
    cvt_hilo<<<(G4 * EDIM / 4 + 255) / 256, 256>>>(Wih0, w0h, w0l, G4 * EDIM);
    gemm_bf16x3<<<dim3(MROWS / 128, G4 / 128), 256, GEMM_SMEM>>>(
        ah, al, w0h, w0l, pre, MROWS, G4, EDIM, bih0, bhh0, 1);

    // remaining weight conversions
    cvt_hilo<<<(G4 * HDIM / 4 + 255) / 256, 256>>>(Wih1, w1h, w1l, G4 * HDIM);
    cvt_hilo<<<(VOCAB * HDIM / 4 + 255) / 256, 256>>>(fc_W, fh, fl, VOCAB * HDIM);

    // layer-0 recurrence (bar reset folded into gemm above)
    lstm_persist<<<NBLK, 256, LSTM_SMEM>>>(pre, Whh0, ah, al);

    // pre1 = hs0 @ Wih1^T + biases (resets bar for lstm1)
    gemm_bf16x3<<<dim3(MROWS / 128, G4 / 128), 256, GEMM_SMEM>>>(
        ah, al, w1h, w1l, pre, MROWS, G4, HDIM, bih1, bhh1, 1);

    // layer-1 recurrence
    lstm_persist<<<NBLK, 256, LSTM_SMEM>>>(pre, Whh1, ah, al);

    // logits = hs1 @ fc_W^T + fc_b
    gemm_bf16x3<<<dim3(MROWS / 128, VOCAB / 128), 256, GEMM_SMEM>>>(
        ah, al, fh, fl, out, MROWS, VOCAB, HDIM, fc_b, nullptr, 0);
}